// round 1
// baseline (speedup 1.0000x reference)
#include <cuda_runtime.h>
#include <cuda_bf16.h>
#include <cstdint>

// Problem constants (fixed-shape problem)
#define N_TOK   4096
#define D_IN    2048
#define D_OUT   2048
#define RANK    16
#define MAX_LORAS 32

// Scratch for A_result [N_TOK, RANK] — __device__ global (no allocation allowed)
__device__ float g_Ares[N_TOK * RANK];

// ---------------------------------------------------------------------------
// Kernel 1: LoRA shrink (bgmv).  One block per token, 128 threads.
// A_result[n, r] = sum_i x[n, i] * lora_A[adapter[n], r, i]
// ---------------------------------------------------------------------------
__global__ __launch_bounds__(128) void lora_shrink_kernel(
    const float* __restrict__ x,
    const int*   __restrict__ adapter_ids,
    const float* __restrict__ lora_A)
{
    __shared__ float xs[D_IN];

    const int n   = blockIdx.x;
    const int tid = threadIdx.x;

    // Cooperative load of the token's x row into shared memory (float4)
    const float4* xg  = reinterpret_cast<const float4*>(x + (size_t)n * D_IN);
    float4*       xs4 = reinterpret_cast<float4*>(xs);
    #pragma unroll
    for (int i = tid; i < D_IN / 4; i += 128) xs4[i] = xg[i];
    __syncthreads();

    const int a    = adapter_ids[n];
    const int warp = tid >> 5;
    const int lane = tid & 31;

    // 4 warps x 4 ranks each = 16 ranks
    #pragma unroll
    for (int rr = 0; rr < 4; rr++) {
        const int r = warp * 4 + rr;
        const float4* Ar = reinterpret_cast<const float4*>(
            lora_A + ((size_t)a * RANK + r) * D_IN);
        float acc = 0.f;
        #pragma unroll 4
        for (int i = lane; i < D_IN / 4; i += 32) {
            float4 av = __ldg(Ar + i);
            float4 xv = xs4[i];
            acc += av.x * xv.x + av.y * xv.y + av.z * xv.z + av.w * xv.w;
        }
        // warp reduction
        #pragma unroll
        for (int off = 16; off > 0; off >>= 1)
            acc += __shfl_down_sync(0xffffffffu, acc, off);
        if (lane == 0) g_Ares[(size_t)n * RANK + r] = acc;
    }
}

// ---------------------------------------------------------------------------
// Kernel 2: fused base GEMM + LoRA expand + bias + per-adapter scale.
// C[n,o] = sum_i x[n,i]*W[o,i] + b[o] + scale[a_n] * sum_r Ares[n,r]*B[a_n,o,r]
// Tiling: BM=BN=128, BK=8, 256 threads, 8x8 per-thread micro-tile,
// double-buffered shared memory.
// ---------------------------------------------------------------------------
#define BM 128
#define BN 128
#define BK 8

__global__ __launch_bounds__(256, 2) void gemm_lora_fused_kernel(
    const float* __restrict__ x,
    const int*   __restrict__ adapter_ids,
    const float* __restrict__ W,
    const float* __restrict__ bias,
    const float* __restrict__ loraB,
    const float* __restrict__ scaling,
    float*       __restrict__ out)
{
    __shared__ float As[2][BK][BM];
    __shared__ float Bs[2][BK][BN];
    __shared__ float AresSh[BM][RANK];
    __shared__ int   adSh[BM];
    __shared__ float scSh[BM];

    const int tid = threadIdx.x;
    const int tx  = tid & 15;        // 0..15 -> column group
    const int ty  = tid >> 4;        // 0..15 -> row group
    const int rowBlock = blockIdx.y * BM;   // token dim
    const int colBlock = blockIdx.x * BN;   // output dim

    // global->shared load mapping: each thread loads one float4 of X and W
    const int loadRow = tid >> 1;          // 0..127
    const int loadCol = (tid & 1) << 2;    // 0 or 4

    const float* Xg = x + (size_t)(rowBlock + loadRow) * D_IN + loadCol;
    const float* Wg = W + (size_t)(colBlock + loadRow) * D_IN + loadCol;

    float acc[8][8];
    #pragma unroll
    for (int i = 0; i < 8; i++)
        #pragma unroll
        for (int j = 0; j < 8; j++) acc[i][j] = 0.f;

    // Kick off epilogue data loads early (Ares rows, adapter ids, scales)
    {
        const float4* ag  = reinterpret_cast<const float4*>(g_Ares + (size_t)rowBlock * RANK);
        float4*       as4 = reinterpret_cast<float4*>(&AresSh[0][0]);
        as4[tid]       = ag[tid];        // 512 float4 total, 256 threads x2
        as4[tid + 256] = ag[tid + 256];
        if (tid < BM) {
            int a = adapter_ids[rowBlock + tid];
            adSh[tid] = a;
            scSh[tid] = scaling[a];
        }
    }

    // Prologue: load tile 0
    float4 xa = *reinterpret_cast<const float4*>(Xg);
    float4 wa = *reinterpret_cast<const float4*>(Wg);
    As[0][loadCol + 0][loadRow] = xa.x;
    As[0][loadCol + 1][loadRow] = xa.y;
    As[0][loadCol + 2][loadRow] = xa.z;
    As[0][loadCol + 3][loadRow] = xa.w;
    Bs[0][loadCol + 0][loadRow] = wa.x;
    Bs[0][loadCol + 1][loadRow] = wa.y;
    Bs[0][loadCol + 2][loadRow] = wa.z;
    Bs[0][loadCol + 3][loadRow] = wa.w;
    __syncthreads();

    const int nTiles = D_IN / BK;   // 256
    int buf = 0;

    for (int kt = 0; kt < nTiles; kt++) {
        float4 xn, wn;
        const bool has_next = (kt + 1 < nTiles);
        if (has_next) {
            xn = *reinterpret_cast<const float4*>(Xg + (size_t)(kt + 1) * BK);
            wn = *reinterpret_cast<const float4*>(Wg + (size_t)(kt + 1) * BK);
        }

        #pragma unroll
        for (int k = 0; k < BK; k++) {
            float af[8], bf[8];
            *reinterpret_cast<float4*>(&af[0]) =
                *reinterpret_cast<const float4*>(&As[buf][k][ty * 8]);
            *reinterpret_cast<float4*>(&af[4]) =
                *reinterpret_cast<const float4*>(&As[buf][k][ty * 8 + 4]);
            *reinterpret_cast<float4*>(&bf[0]) =
                *reinterpret_cast<const float4*>(&Bs[buf][k][tx * 8]);
            *reinterpret_cast<float4*>(&bf[4]) =
                *reinterpret_cast<const float4*>(&Bs[buf][k][tx * 8 + 4]);
            #pragma unroll
            for (int i = 0; i < 8; i++)
                #pragma unroll
                for (int j = 0; j < 8; j++)
                    acc[i][j] += af[i] * bf[j];
        }

        if (has_next) {
            buf ^= 1;
            As[buf][loadCol + 0][loadRow] = xn.x;
            As[buf][loadCol + 1][loadRow] = xn.y;
            As[buf][loadCol + 2][loadRow] = xn.z;
            As[buf][loadCol + 3][loadRow] = xn.w;
            Bs[buf][loadCol + 0][loadRow] = wn.x;
            Bs[buf][loadCol + 1][loadRow] = wn.y;
            Bs[buf][loadCol + 2][loadRow] = wn.z;
            Bs[buf][loadCol + 3][loadRow] = wn.w;
            __syncthreads();
        }
    }

    // ---- Epilogue: bias + per-token LoRA expand + scale, vectorized store ----
    float bb[8];
    #pragma unroll
    for (int j = 0; j < 8; j++)
        bb[j] = __ldg(bias + colBlock + tx * 8 + j);

    #pragma unroll
    for (int i = 0; i < 8; i++) {
        const int   rlocal = ty * 8 + i;
        const int   n      = rowBlock + rlocal;
        const int   a      = adSh[rlocal];
        const float sc     = scSh[rlocal];

        float4 ar0 = *reinterpret_cast<const float4*>(&AresSh[rlocal][0]);
        float4 ar1 = *reinterpret_cast<const float4*>(&AresSh[rlocal][4]);
        float4 ar2 = *reinterpret_cast<const float4*>(&AresSh[rlocal][8]);
        float4 ar3 = *reinterpret_cast<const float4*>(&AresSh[rlocal][12]);

        const float* Bbase = loraB + (size_t)a * D_OUT * RANK;

        float res[8];
        #pragma unroll
        for (int j = 0; j < 8; j++) {
            const int o = colBlock + tx * 8 + j;
            const float4* Bp = reinterpret_cast<const float4*>(Bbase + (size_t)o * RANK);
            float4 b0 = __ldg(Bp + 0);
            float4 b1 = __ldg(Bp + 1);
            float4 b2 = __ldg(Bp + 2);
            float4 b3 = __ldg(Bp + 3);
            float s = ar0.x * b0.x + ar0.y * b0.y + ar0.z * b0.z + ar0.w * b0.w
                    + ar1.x * b1.x + ar1.y * b1.y + ar1.z * b1.z + ar1.w * b1.w
                    + ar2.x * b2.x + ar2.y * b2.y + ar2.z * b2.z + ar2.w * b2.w
                    + ar3.x * b3.x + ar3.y * b3.y + ar3.z * b3.z + ar3.w * b3.w;
            res[j] = acc[i][j] + bb[j] + sc * s;
        }

        float* orow = out + (size_t)n * D_OUT + colBlock + tx * 8;
        float4 o0 = make_float4(res[0], res[1], res[2], res[3]);
        float4 o1 = make_float4(res[4], res[5], res[6], res[7]);
        *reinterpret_cast<float4*>(orow + 0) = o0;
        *reinterpret_cast<float4*>(orow + 4) = o1;
    }
}

// ---------------------------------------------------------------------------
// Launch
// ---------------------------------------------------------------------------
extern "C" void kernel_launch(void* const* d_in, const int* in_sizes, int n_in,
                              void* d_out, int out_size)
{
    const float* x           = (const float*)d_in[0];
    const int*   adapter_ids = (const int*)  d_in[1];
    const float* W_base      = (const float*)d_in[2];
    const float* b_base      = (const float*)d_in[3];
    const float* lora_A      = (const float*)d_in[4];
    const float* lora_B      = (const float*)d_in[5];
    const float* lora_scal   = (const float*)d_in[6];
    float*       out         = (float*)d_out;

    lora_shrink_kernel<<<N_TOK, 128>>>(x, adapter_ids, lora_A);

    dim3 grid(D_OUT / BN, N_TOK / BM);   // (16, 32)
    gemm_lora_fused_kernel<<<grid, 256>>>(x, adapter_ids, W_base, b_base,
                                          lora_B, lora_scal, out);
}

// round 4
// speedup vs baseline: 1.9227x; 1.9227x over previous
#include <cuda_runtime.h>
#include <cuda_bf16.h>
#include <cstdint>

// ---------------- problem constants ----------------
#define N_TOK 4096
#define D_IN  2048
#define D_OUT 2048
#define RANK  16

// ---------------- GEMM tiling ----------------
#define BM 128
#define BN 128
#define BK 32                 // bf16 elems per K-tile
#define NKT (D_IN / BK)       // 64
#define TPB 256
#define STAGES 3

#define ROW_STRIDE_B 80       // bytes per SMEM row (40 bf16): conflict-free ldmatrix
#define ARR_BYTES (128 * ROW_STRIDE_B)   // 10240 per tile array
#define STAGE_BYTES (4 * ARR_BYTES)      // Ah, Al, Bh, Bl
#define DYN_BYTES (STAGES * STAGE_BYTES) // 122880

// ---------------- device scratch (no runtime allocation allowed) ----------------
__device__ float          g_Ares[N_TOK * RANK];
__device__ __nv_bfloat16  g_Xh[N_TOK * D_IN];
__device__ __nv_bfloat16  g_Xl[N_TOK * D_IN];
__device__ __nv_bfloat16  g_Wh[D_OUT * D_IN];
__device__ __nv_bfloat16  g_Wl[D_OUT * D_IN];

// ---------------- PTX helpers (baseline-portable only: sm_80-era ops) ----------------
__device__ __forceinline__ uint32_t smem_u32(const void* p) {
    uint32_t a;
    asm("{ .reg .u64 t; cvta.to.shared.u64 t, %1; cvt.u32.u64 %0, t; }" : "=r"(a) : "l"(p));
    return a;
}
#define CP16(dst, src) \
    asm volatile("cp.async.cg.shared.global [%0], [%1], 16;" :: "r"(dst), "l"(src) : "memory")
#define CP_COMMIT()  asm volatile("cp.async.commit_group;" ::: "memory")
#define CP_WAIT(n)   asm volatile("cp.async.wait_group %0;" :: "n"(n) : "memory")

__device__ __forceinline__ void ldsm4(uint32_t* r, uint32_t addr) {
    asm volatile("ldmatrix.sync.aligned.m8n8.x4.shared.b16 {%0,%1,%2,%3}, [%4];"
        : "=r"(r[0]), "=r"(r[1]), "=r"(r[2]), "=r"(r[3]) : "r"(addr));
}
__device__ __forceinline__ void mma_bf16(float* d, const uint32_t* a,
                                         uint32_t b0, uint32_t b1) {
    asm volatile(
        "mma.sync.aligned.m16n8k16.row.col.f32.bf16.bf16.f32 "
        "{%0,%1,%2,%3}, {%4,%5,%6,%7}, {%8,%9}, {%0,%1,%2,%3};"
        : "+f"(d[0]), "+f"(d[1]), "+f"(d[2]), "+f"(d[3])
        : "r"(a[0]), "r"(a[1]), "r"(a[2]), "r"(a[3]), "r"(b0), "r"(b1));
}

// ---------------------------------------------------------------------------
// Kernel A: split fp32 X and W into bf16 hi + bf16 residual
// ---------------------------------------------------------------------------
__global__ __launch_bounds__(256) void convert_split_kernel(
    const float* __restrict__ x, const float* __restrict__ w)
{
    const int idx = blockIdx.x * blockDim.x + threadIdx.x;
    const int NX4 = N_TOK * D_IN / 4;
    const int NW4 = D_OUT * D_IN / 4;
    if (idx < NX4) {
        float4 v = reinterpret_cast<const float4*>(x)[idx];
        float f[4] = {v.x, v.y, v.z, v.w};
        __nv_bfloat16 h[4], l[4];
        #pragma unroll
        for (int j = 0; j < 4; j++) {
            h[j] = __float2bfloat16(f[j]);
            l[j] = __float2bfloat16(f[j] - __bfloat162float(h[j]));
        }
        *reinterpret_cast<uint2*>(&g_Xh[(size_t)idx * 4]) = *reinterpret_cast<uint2*>(h);
        *reinterpret_cast<uint2*>(&g_Xl[(size_t)idx * 4]) = *reinterpret_cast<uint2*>(l);
    }
    if (idx < NW4) {
        float4 v = reinterpret_cast<const float4*>(w)[idx];
        float f[4] = {v.x, v.y, v.z, v.w};
        __nv_bfloat16 h[4], l[4];
        #pragma unroll
        for (int j = 0; j < 4; j++) {
            h[j] = __float2bfloat16(f[j]);
            l[j] = __float2bfloat16(f[j] - __bfloat162float(h[j]));
        }
        *reinterpret_cast<uint2*>(&g_Wh[(size_t)idx * 4]) = *reinterpret_cast<uint2*>(h);
        *reinterpret_cast<uint2*>(&g_Wl[(size_t)idx * 4]) = *reinterpret_cast<uint2*>(l);
    }
}

// ---------------------------------------------------------------------------
// Kernel B: LoRA shrink (bgmv), fp32 exact
// ---------------------------------------------------------------------------
__global__ __launch_bounds__(128) void lora_shrink_kernel(
    const float* __restrict__ x,
    const int*   __restrict__ adapter_ids,
    const float* __restrict__ lora_A)
{
    __shared__ float xs[D_IN];
    const int n = blockIdx.x, tid = threadIdx.x;
    const float4* xg  = reinterpret_cast<const float4*>(x + (size_t)n * D_IN);
    float4*       xs4 = reinterpret_cast<float4*>(xs);
    #pragma unroll
    for (int i = tid; i < D_IN / 4; i += 128) xs4[i] = xg[i];
    __syncthreads();

    const int a = adapter_ids[n];
    const int warp = tid >> 5, lane = tid & 31;
    #pragma unroll
    for (int rr = 0; rr < 4; rr++) {
        const int r = warp * 4 + rr;
        const float4* Ar = reinterpret_cast<const float4*>(lora_A + ((size_t)a * RANK + r) * D_IN);
        float acc = 0.f;
        #pragma unroll 4
        for (int i = lane; i < D_IN / 4; i += 32) {
            float4 av = __ldg(Ar + i);
            float4 xv = xs4[i];
            acc += av.x * xv.x + av.y * xv.y + av.z * xv.z + av.w * xv.w;
        }
        #pragma unroll
        for (int off = 16; off > 0; off >>= 1) acc += __shfl_down_sync(0xffffffffu, acc, off);
        if (lane == 0) g_Ares[(size_t)n * RANK + r] = acc;
    }
}

// ---------------------------------------------------------------------------
// Kernel C: mma.sync bf16x3 GEMM + fused LoRA expand epilogue.
// Grid: (D_OUT/BN, N_TOK/BM) = (16, 32). 256 threads = 8 warps in 2x4:
//   warpM (0..1) owns 64 token-rows, warpN (0..3) owns 32 output-cols.
// Accumulates xh*wh + xl*wh + xh*wl in fp32 (split-bf16, 3 MMAs per frag).
// ---------------------------------------------------------------------------
__global__ __launch_bounds__(TPB) void gemm_mma_kernel(
    const int*   __restrict__ adapter_ids,
    const float* __restrict__ bias,
    const float* __restrict__ loraB,
    const float* __restrict__ scaling,
    float*       __restrict__ out)
{
    extern __shared__ char dsm[];
    __shared__ float AresSh[BM][RANK];
    __shared__ int   adSh[BM];
    __shared__ float scSh[BM];

    const int tid  = threadIdx.x;
    const int wid  = tid >> 5, lane = tid & 31;
    const int warpM = wid >> 2;          // 0..1
    const int warpN = wid & 3;           // 0..3
    const int rowBlock = blockIdx.y * BM;
    const int colBlock = blockIdx.x * BN;

    const uint32_t dynb = smem_u32(dsm);

    // epilogue data preload (Ares rows, adapter ids, scales)
    {
        const float4* ag  = reinterpret_cast<const float4*>(g_Ares + (size_t)rowBlock * RANK);
        float4*       as4 = reinterpret_cast<float4*>(&AresSh[0][0]);
        as4[tid]       = ag[tid];
        as4[tid + 256] = ag[tid + 256];
        if (tid < BM) {
            int a = adapter_ids[rowBlock + tid];
            adSh[tid] = a;
            scSh[tid] = scaling[a];
        }
    }

    // global->shared mapping: 512 16B-chunks per array, 2 per thread
    const int ldRow  = tid >> 2;           // rows 0..63
    const int ldCc   = (tid & 3) * 16;     // 4 chunks cover 64B (= BK bf16)
    const int ldRow2 = ldRow + 64;         // rows 64..127

    const char* srcXh = (const char*)(g_Xh + (size_t)rowBlock * D_IN);
    const char* srcXl = (const char*)(g_Xl + (size_t)rowBlock * D_IN);
    const char* srcWh = (const char*)(g_Wh + (size_t)colBlock * D_IN);
    const char* srcWl = (const char*)(g_Wl + (size_t)colBlock * D_IN);

    auto load_tile = [&](int kt, int stg) {
        const uint32_t sb = dynb + stg * STAGE_BYTES;
        const size_t koff = (size_t)kt * (BK * 2);
        const uint32_t d0 = ldRow * ROW_STRIDE_B + ldCc;
        const uint32_t d1 = ldRow2 * ROW_STRIDE_B + ldCc;
        const size_t s0 = (size_t)ldRow  * (D_IN * 2) + koff + ldCc;
        const size_t s1 = (size_t)ldRow2 * (D_IN * 2) + koff + ldCc;
        CP16(sb + 0 * ARR_BYTES + d0, srcXh + s0);
        CP16(sb + 0 * ARR_BYTES + d1, srcXh + s1);
        CP16(sb + 1 * ARR_BYTES + d0, srcXl + s0);
        CP16(sb + 1 * ARR_BYTES + d1, srcXl + s1);
        CP16(sb + 2 * ARR_BYTES + d0, srcWh + s0);
        CP16(sb + 2 * ARR_BYTES + d1, srcWh + s1);
        CP16(sb + 3 * ARR_BYTES + d0, srcWl + s0);
        CP16(sb + 3 * ARR_BYTES + d1, srcWl + s1);
        CP_COMMIT();
    };

    float acc[4][4][4];
    #pragma unroll
    for (int m = 0; m < 4; m++)
        #pragma unroll
        for (int n = 0; n < 4; n++)
            #pragma unroll
            for (int k = 0; k < 4; k++) acc[m][n][k] = 0.f;

    // ldmatrix.x4 canonical addressing: threads 0-15 -> rows, 16-31 -> +16B col
    const uint32_t lmRow   = lane & 15;
    const uint32_t lmChunk = (lane >> 4) * 16;
    const uint32_t aByte = (warpM * 64 + lmRow) * ROW_STRIDE_B + lmChunk;
    const uint32_t bByte = (warpN * 32 + lmRow) * ROW_STRIDE_B + lmChunk;

    load_tile(0, 0);
    load_tile(1, 1);

    for (int kt = 0; kt < NKT; kt++) {
        const int stg = kt % STAGES;
        CP_WAIT(STAGES - 2);
        __syncthreads();
        if (kt + STAGES - 1 < NKT) load_tile(kt + STAGES - 1, (kt + STAGES - 1) % STAGES);

        const uint32_t sb = dynb + stg * STAGE_BYTES;
        const uint32_t aH = sb + 0 * ARR_BYTES + aByte;
        const uint32_t aL = sb + 1 * ARR_BYTES + aByte;
        const uint32_t bH = sb + 2 * ARR_BYTES + bByte;
        const uint32_t bL = sb + 3 * ARR_BYTES + bByte;

        #pragma unroll
        for (int s = 0; s < 2; s++) {          // two k16 steps per BK=32 tile
            const uint32_t ko = s * 32;        // 16 bf16 = 32 bytes
            uint32_t ah[4][4], al[4][4], bh[2][4], bl[2][4];
            #pragma unroll
            for (int m = 0; m < 4; m++) {
                ldsm4(ah[m], aH + m * 16 * ROW_STRIDE_B + ko);
                ldsm4(al[m], aL + m * 16 * ROW_STRIDE_B + ko);
            }
            #pragma unroll
            for (int g = 0; g < 2; g++) {
                ldsm4(bh[g], bH + g * 16 * ROW_STRIDE_B + ko);
                ldsm4(bl[g], bL + g * 16 * ROW_STRIDE_B + ko);
            }
            #pragma unroll
            for (int m = 0; m < 4; m++)
                #pragma unroll
                for (int ng = 0; ng < 4; ng++) {
                    const int g = ng >> 1, sub = ng & 1;
                    mma_bf16(acc[m][ng], ah[m], bh[g][sub], bh[g][sub + 2]);
                    mma_bf16(acc[m][ng], al[m], bh[g][sub], bh[g][sub + 2]);
                    mma_bf16(acc[m][ng], ah[m], bl[g][sub], bl[g][sub + 2]);
                }
        }
    }

    // ---- epilogue: acc + bias + scale * (Ares . loraB[a, o, :]) ----
    const int gID = lane >> 2, tig = lane & 3;
    #pragma unroll
    for (int m = 0; m < 4; m++) {
        #pragma unroll
        for (int h = 0; h < 2; h++) {
            const int rl = warpM * 64 + m * 16 + gID + h * 8;
            const int n  = rowBlock + rl;
            const int a  = adSh[rl];
            const float sc = scSh[rl];
            const float4 ar0 = *reinterpret_cast<const float4*>(&AresSh[rl][0]);
            const float4 ar1 = *reinterpret_cast<const float4*>(&AresSh[rl][4]);
            const float4 ar2 = *reinterpret_cast<const float4*>(&AresSh[rl][8]);
            const float4 ar3 = *reinterpret_cast<const float4*>(&AresSh[rl][12]);
            const float* Bb = loraB + (size_t)a * D_OUT * RANK;
            float* orow = out + (size_t)n * D_OUT + colBlock;

            #pragma unroll
            for (int ng = 0; ng < 4; ng++) {
                const int c0 = warpN * 32 + ng * 8 + 2 * tig;
                float r2[2];
                #pragma unroll
                for (int q = 0; q < 2; q++) {
                    const int o = colBlock + c0 + q;
                    const float4* Bp = reinterpret_cast<const float4*>(Bb + (size_t)o * RANK);
                    float4 b0 = __ldg(Bp + 0), b1 = __ldg(Bp + 1);
                    float4 b2 = __ldg(Bp + 2), b3 = __ldg(Bp + 3);
                    float sdot = ar0.x*b0.x + ar0.y*b0.y + ar0.z*b0.z + ar0.w*b0.w
                               + ar1.x*b1.x + ar1.y*b1.y + ar1.z*b1.z + ar1.w*b1.w
                               + ar2.x*b2.x + ar2.y*b2.y + ar2.z*b2.z + ar2.w*b2.w
                               + ar3.x*b3.x + ar3.y*b3.y + ar3.z*b3.z + ar3.w*b3.w;
                    r2[q] = acc[m][ng][h * 2 + q] + __ldg(bias + o) + sc * sdot;
                }
                *reinterpret_cast<float2*>(orow + c0) = make_float2(r2[0], r2[1]);
            }
        }
    }
}

// ---------------------------------------------------------------------------
// Launch
// ---------------------------------------------------------------------------
extern "C" void kernel_launch(void* const* d_in, const int* in_sizes, int n_in,
                              void* d_out, int out_size)
{
    const float* x           = (const float*)d_in[0];
    const int*   adapter_ids = (const int*)  d_in[1];
    const float* W_base      = (const float*)d_in[2];
    const float* b_base      = (const float*)d_in[3];
    const float* lora_A      = (const float*)d_in[4];
    const float* lora_B      = (const float*)d_in[5];
    const float* lora_scal   = (const float*)d_in[6];
    float*       out         = (float*)d_out;

    cudaFuncSetAttribute(gemm_mma_kernel,
                         cudaFuncAttributeMaxDynamicSharedMemorySize, DYN_BYTES);

    convert_split_kernel<<<(N_TOK * D_IN / 4 + 255) / 256, 256>>>(x, W_base);
    lora_shrink_kernel<<<N_TOK, 128>>>(x, adapter_ids, lora_A);

    dim3 grid(D_OUT / BN, N_TOK / BM);   // (16, 32)
    gemm_mma_kernel<<<grid, TPB, DYN_BYTES>>>(adapter_ids, b_base, lora_B,
                                              lora_scal, out);
}

// round 5
// speedup vs baseline: 3.7203x; 1.9349x over previous
#include <cuda_runtime.h>
#include <cuda_fp16.h>
#include <cstdint>

// ---------------- problem constants ----------------
#define N_TOK 4096
#define D_IN  2048
#define D_OUT 2048
#define RANK  16

// ---------------- GEMM tiling ----------------
#define BM 128
#define BN 128
#define BK 32                 // fp16 elems per K-tile
#define NKT (D_IN / BK)       // 64
#define TPB 256
#define STAGES 4

#define ROW_STRIDE_B 80       // bytes per SMEM row (40 fp16): conflict-free ldmatrix
#define ARR_BYTES (128 * ROW_STRIDE_B)   // 10240 per tile array
#define STAGE_BYTES (2 * ARR_BYTES)      // A, B            (20480)
#define DYN_BYTES (STAGES * STAGE_BYTES) // 81920 -> 2 CTAs/SM

// ---------------- device scratch (no runtime allocation allowed) ----------------
__device__ float  g_Ares[N_TOK * RANK];
__device__ __half g_Xi[N_TOK * D_IN];
__device__ __half g_Wi[D_OUT * D_IN];

// ---------------- PTX helpers (baseline-portable: sm_80-era ops) ----------------
__device__ __forceinline__ uint32_t smem_u32(const void* p) {
    uint32_t a;
    asm("{ .reg .u64 t; cvta.to.shared.u64 t, %1; cvt.u32.u64 %0, t; }" : "=r"(a) : "l"(p));
    return a;
}
#define CP16(dst, src) \
    asm volatile("cp.async.cg.shared.global [%0], [%1], 16;" :: "r"(dst), "l"(src) : "memory")
#define CP_COMMIT()  asm volatile("cp.async.commit_group;" ::: "memory")
#define CP_WAIT(n)   asm volatile("cp.async.wait_group %0;" :: "n"(n) : "memory")

__device__ __forceinline__ void ldsm4(uint32_t* r, uint32_t addr) {
    asm volatile("ldmatrix.sync.aligned.m8n8.x4.shared.b16 {%0,%1,%2,%3}, [%4];"
        : "=r"(r[0]), "=r"(r[1]), "=r"(r[2]), "=r"(r[3]) : "r"(addr));
}
__device__ __forceinline__ void mma_f16(float* d, const uint32_t* a,
                                        uint32_t b0, uint32_t b1) {
    asm volatile(
        "mma.sync.aligned.m16n8k16.row.col.f32.f16.f16.f32 "
        "{%0,%1,%2,%3}, {%4,%5,%6,%7}, {%8,%9}, {%0,%1,%2,%3};"
        : "+f"(d[0]), "+f"(d[1]), "+f"(d[2]), "+f"(d[3])
        : "r"(a[0]), "r"(a[1]), "r"(a[2]), "r"(a[3]), "r"(b0), "r"(b1));
}

// ---------------------------------------------------------------------------
// Kernel A: convert fp32 X and W to fp16 (single pass; rel_err ~2e-4 by
// independent-rounding statistics over K=2048, well under the 1e-3 gate)
// ---------------------------------------------------------------------------
__global__ __launch_bounds__(256) void convert_f16_kernel(
    const float* __restrict__ x, const float* __restrict__ w)
{
    const int idx = blockIdx.x * blockDim.x + threadIdx.x;   // float4 index
    const int NX4 = N_TOK * D_IN / 4;
    const int NW4 = D_OUT * D_IN / 4;
    if (idx < NX4) {
        float4 v = reinterpret_cast<const float4*>(x)[idx];
        __half h[4] = {__float2half_rn(v.x), __float2half_rn(v.y),
                       __float2half_rn(v.z), __float2half_rn(v.w)};
        *reinterpret_cast<uint2*>(&g_Xi[(size_t)idx * 4]) = *reinterpret_cast<uint2*>(h);
    }
    if (idx < NW4) {
        float4 v = reinterpret_cast<const float4*>(w)[idx];
        __half h[4] = {__float2half_rn(v.x), __float2half_rn(v.y),
                       __float2half_rn(v.z), __float2half_rn(v.w)};
        *reinterpret_cast<uint2*>(&g_Wi[(size_t)idx * 4]) = *reinterpret_cast<uint2*>(h);
    }
}

// ---------------------------------------------------------------------------
// Kernel B: LoRA shrink (bgmv), fp32 exact
// ---------------------------------------------------------------------------
__global__ __launch_bounds__(128) void lora_shrink_kernel(
    const float* __restrict__ x,
    const int*   __restrict__ adapter_ids,
    const float* __restrict__ lora_A)
{
    __shared__ float xs[D_IN];
    const int n = blockIdx.x, tid = threadIdx.x;
    const float4* xg  = reinterpret_cast<const float4*>(x + (size_t)n * D_IN);
    float4*       xs4 = reinterpret_cast<float4*>(xs);
    #pragma unroll
    for (int i = tid; i < D_IN / 4; i += 128) xs4[i] = xg[i];
    __syncthreads();

    const int a = adapter_ids[n];
    const int warp = tid >> 5, lane = tid & 31;
    #pragma unroll
    for (int rr = 0; rr < 4; rr++) {
        const int r = warp * 4 + rr;
        const float4* Ar = reinterpret_cast<const float4*>(lora_A + ((size_t)a * RANK + r) * D_IN);
        float acc = 0.f;
        #pragma unroll 4
        for (int i = lane; i < D_IN / 4; i += 32) {
            float4 av = __ldg(Ar + i);
            float4 xv = xs4[i];
            acc += av.x * xv.x + av.y * xv.y + av.z * xv.z + av.w * xv.w;
        }
        #pragma unroll
        for (int off = 16; off > 0; off >>= 1) acc += __shfl_down_sync(0xffffffffu, acc, off);
        if (lane == 0) g_Ares[(size_t)n * RANK + r] = acc;
    }
}

// ---------------------------------------------------------------------------
// Kernel C: fp16 mma.sync GEMM + fused LoRA expand epilogue.
// Grid (16, 32); 256 threads = 8 warps (2x4); warp tile 64x32.
// __launch_bounds__(256, 2): 2 CTAs/SM (80KB dyn smem each), 16 warps/SM.
// ---------------------------------------------------------------------------
__global__ __launch_bounds__(TPB, 2) void gemm_mma_kernel(
    const int*   __restrict__ adapter_ids,
    const float* __restrict__ bias,
    const float* __restrict__ loraB,
    const float* __restrict__ scaling,
    float*       __restrict__ out)
{
    extern __shared__ char dsm[];
    __shared__ float AresSh[BM][RANK];
    __shared__ int   adSh[BM];
    __shared__ float scSh[BM];

    const int tid  = threadIdx.x;
    const int wid  = tid >> 5, lane = tid & 31;
    const int warpM = wid >> 2;          // 0..1 (64 rows)
    const int warpN = wid & 3;           // 0..3 (32 cols)
    const int rowBlock = blockIdx.y * BM;
    const int colBlock = blockIdx.x * BN;

    const uint32_t dynb = smem_u32(dsm);

    // epilogue data preload
    {
        const float4* ag  = reinterpret_cast<const float4*>(g_Ares + (size_t)rowBlock * RANK);
        float4*       as4 = reinterpret_cast<float4*>(&AresSh[0][0]);
        as4[tid]       = ag[tid];
        as4[tid + 256] = ag[tid + 256];
        if (tid < BM) {
            int a = adapter_ids[rowBlock + tid];
            adSh[tid] = a;
            scSh[tid] = scaling[a];
        }
    }

    // global->shared: 512 16B-chunks per array, 2 per thread per array
    const int ldRow  = tid >> 2;           // rows 0..63
    const int ldCc   = (tid & 3) * 16;
    const int ldRow2 = ldRow + 64;

    const char* srcX = (const char*)(g_Xi + (size_t)rowBlock * D_IN);
    const char* srcW = (const char*)(g_Wi + (size_t)colBlock * D_IN);

    auto load_tile = [&](int kt, int stg) {
        const uint32_t sb = dynb + stg * STAGE_BYTES;
        const size_t koff = (size_t)kt * (BK * 2);
        const uint32_t d0 = ldRow * ROW_STRIDE_B + ldCc;
        const uint32_t d1 = ldRow2 * ROW_STRIDE_B + ldCc;
        const size_t s0 = (size_t)ldRow  * (D_IN * 2) + koff + ldCc;
        const size_t s1 = (size_t)ldRow2 * (D_IN * 2) + koff + ldCc;
        CP16(sb + 0 * ARR_BYTES + d0, srcX + s0);
        CP16(sb + 0 * ARR_BYTES + d1, srcX + s1);
        CP16(sb + 1 * ARR_BYTES + d0, srcW + s0);
        CP16(sb + 1 * ARR_BYTES + d1, srcW + s1);
        CP_COMMIT();
    };

    float acc[4][4][4];
    #pragma unroll
    for (int m = 0; m < 4; m++)
        #pragma unroll
        for (int n = 0; n < 4; n++)
            #pragma unroll
            for (int k = 0; k < 4; k++) acc[m][n][k] = 0.f;

    const uint32_t lmRow   = lane & 15;
    const uint32_t lmChunk = (lane >> 4) * 16;
    const uint32_t aByte = (warpM * 64 + lmRow) * ROW_STRIDE_B + lmChunk;
    const uint32_t bByte = (warpN * 32 + lmRow) * ROW_STRIDE_B + lmChunk;

    // prologue: fill STAGES-1 stages
    load_tile(0, 0);
    load_tile(1, 1);
    load_tile(2, 2);

    for (int kt = 0; kt < NKT; kt++) {
        const int stg = kt % STAGES;
        CP_WAIT(STAGES - 2);
        __syncthreads();
        if (kt + STAGES - 1 < NKT) load_tile(kt + STAGES - 1, (kt + STAGES - 1) % STAGES);

        const uint32_t sb = dynb + stg * STAGE_BYTES;
        const uint32_t aB = sb + 0 * ARR_BYTES + aByte;
        const uint32_t bB = sb + 1 * ARR_BYTES + bByte;

        #pragma unroll
        for (int s = 0; s < 2; s++) {          // two k16 steps per BK=32
            const uint32_t ko = s * 32;
            uint32_t ah[4][4], bh[2][4];
            #pragma unroll
            for (int m = 0; m < 4; m++)
                ldsm4(ah[m], aB + m * 16 * ROW_STRIDE_B + ko);
            #pragma unroll
            for (int g = 0; g < 2; g++)
                ldsm4(bh[g], bB + g * 16 * ROW_STRIDE_B + ko);
            #pragma unroll
            for (int m = 0; m < 4; m++)
                #pragma unroll
                for (int ng = 0; ng < 4; ng++) {
                    const int g = ng >> 1, sub = ng & 1;
                    mma_f16(acc[m][ng], ah[m], bh[g][sub], bh[g][sub + 2]);
                }
        }
    }

    // ---- epilogue: acc + bias + scale * (Ares . loraB[a, o, :]) ----
    const int gID = lane >> 2, tig = lane & 3;
    #pragma unroll
    for (int m = 0; m < 4; m++) {
        #pragma unroll
        for (int h = 0; h < 2; h++) {
            const int rl = warpM * 64 + m * 16 + gID + h * 8;
            const int n  = rowBlock + rl;
            const int a  = adSh[rl];
            const float sc = scSh[rl];
            const float4 ar0 = *reinterpret_cast<const float4*>(&AresSh[rl][0]);
            const float4 ar1 = *reinterpret_cast<const float4*>(&AresSh[rl][4]);
            const float4 ar2 = *reinterpret_cast<const float4*>(&AresSh[rl][8]);
            const float4 ar3 = *reinterpret_cast<const float4*>(&AresSh[rl][12]);
            const float* Bb = loraB + (size_t)a * D_OUT * RANK;
            float* orow = out + (size_t)n * D_OUT + colBlock;

            #pragma unroll
            for (int ng = 0; ng < 4; ng++) {
                const int c0 = warpN * 32 + ng * 8 + 2 * tig;
                float r2[2];
                #pragma unroll
                for (int q = 0; q < 2; q++) {
                    const int o = colBlock + c0 + q;
                    const float4* Bp = reinterpret_cast<const float4*>(Bb + (size_t)o * RANK);
                    float4 b0 = __ldg(Bp + 0), b1 = __ldg(Bp + 1);
                    float4 b2 = __ldg(Bp + 2), b3 = __ldg(Bp + 3);
                    float sdot = ar0.x*b0.x + ar0.y*b0.y + ar0.z*b0.z + ar0.w*b0.w
                               + ar1.x*b1.x + ar1.y*b1.y + ar1.z*b1.z + ar1.w*b1.w
                               + ar2.x*b2.x + ar2.y*b2.y + ar2.z*b2.z + ar2.w*b2.w
                               + ar3.x*b3.x + ar3.y*b3.y + ar3.z*b3.z + ar3.w*b3.w;
                    r2[q] = acc[m][ng][h * 2 + q] + __ldg(bias + o) + sc * sdot;
                }
                *reinterpret_cast<float2*>(orow + c0) = make_float2(r2[0], r2[1]);
            }
        }
    }
}

// ---------------------------------------------------------------------------
// Launch
// ---------------------------------------------------------------------------
extern "C" void kernel_launch(void* const* d_in, const int* in_sizes, int n_in,
                              void* d_out, int out_size)
{
    const float* x           = (const float*)d_in[0];
    const int*   adapter_ids = (const int*)  d_in[1];
    const float* W_base      = (const float*)d_in[2];
    const float* b_base      = (const float*)d_in[3];
    const float* lora_A      = (const float*)d_in[4];
    const float* lora_B      = (const float*)d_in[5];
    const float* lora_scal   = (const float*)d_in[6];
    float*       out         = (float*)d_out;

    cudaFuncSetAttribute(gemm_mma_kernel,
                         cudaFuncAttributeMaxDynamicSharedMemorySize, DYN_BYTES);

    convert_f16_kernel<<<(N_TOK * D_IN / 4 + 255) / 256, 256>>>(x, W_base);
    lora_shrink_kernel<<<N_TOK, 128>>>(x, adapter_ids, lora_A);

    dim3 grid(D_OUT / BN, N_TOK / BM);   // (16, 32)
    gemm_mma_kernel<<<grid, TPB, DYN_BYTES>>>(adapter_ids, b_base, lora_B,
                                              lora_scal, out);
}

// round 9
// speedup vs baseline: 5.2319x; 1.4063x over previous
#include <cuda_runtime.h>
#include <cuda_fp16.h>
#include <cstdint>

// ---------------- problem constants ----------------
#define N_TOK 4096
#define D_IN  2048
#define D_OUT 2048
#define RANK  16
#define MAX_LORAS 32

// ---------------- GEMM tiling ----------------
#define BM 128
#define BN 128
#define BK 32                 // fp16 elems per K-tile
#define NKT (D_IN / BK)       // 64
#define TPB 256
#define STAGES 4
#define NTILES ((N_TOK / BM) * (D_OUT / BN))   // 512
#define GRID_PERSIST 304      // 2 CTAs/SM x 152 SMs (GB300)

#define ROW_STRIDE_B 80       // bytes per SMEM row (40 fp16): conflict-free ldmatrix
#define ARR_BYTES (128 * ROW_STRIDE_B)   // 10240 per tile array
#define STAGE_BYTES (2 * ARR_BYTES)      // A, B  (20480)
#define DYN_BYTES (STAGES * STAGE_BYTES) // 81920 -> 2 CTAs/SM

// ---------------- device scratch (no runtime allocation allowed) ----------------
__device__ __align__(16) float  g_Ares[N_TOK * RANK];
__device__ __align__(16) __half g_Xi[N_TOK * D_IN];
__device__ __align__(16) __half g_Wi[D_OUT * D_IN];
__device__ __align__(16) __half g_Ai[MAX_LORAS * RANK * D_IN];
__device__ __align__(16) __half g_Bi[MAX_LORAS * D_OUT * RANK];

// ---------------- PTX helpers (baseline-portable: sm_80-era ops) ----------------
__device__ __forceinline__ uint32_t smem_u32(const void* p) {
    uint32_t a;
    asm("{ .reg .u64 t; cvta.to.shared.u64 t, %1; cvt.u32.u64 %0, t; }" : "=r"(a) : "l"(p));
    return a;
}
#define CP16(dst, src) \
    asm volatile("cp.async.cg.shared.global [%0], [%1], 16;" :: "r"(dst), "l"(src) : "memory")
#define CP_COMMIT()  asm volatile("cp.async.commit_group;" ::: "memory")
#define CP_WAIT(n)   asm volatile("cp.async.wait_group %0;" :: "n"(n) : "memory")

__device__ __forceinline__ void ldsm4(uint32_t* r, uint32_t addr) {
    asm volatile("ldmatrix.sync.aligned.m8n8.x4.shared.b16 {%0,%1,%2,%3}, [%4];"
        : "=r"(r[0]), "=r"(r[1]), "=r"(r[2]), "=r"(r[3]) : "r"(addr));
}
__device__ __forceinline__ void mma_f16(float* d, const uint32_t* a,
                                        uint32_t b0, uint32_t b1) {
    asm volatile(
        "mma.sync.aligned.m16n8k16.row.col.f32.f16.f16.f32 "
        "{%0,%1,%2,%3}, {%4,%5,%6,%7}, {%8,%9}, {%0,%1,%2,%3};"
        : "+f"(d[0]), "+f"(d[1]), "+f"(d[2]), "+f"(d[3])
        : "r"(a[0]), "r"(a[1]), "r"(a[2]), "r"(a[3]), "r"(b0), "r"(b1));
}
__device__ __forceinline__ float dot_h2(float acc, uint32_t h2, float a0, float a1) {
    float2 f = __half22float2(*reinterpret_cast<__half2*>(&h2));
    return acc + a0 * f.x + a1 * f.y;
}
// fp32 float4 -> packed fp16x4 without local-array reinterpret tricks
__device__ __forceinline__ uint2 f4_to_h4(float4 v) {
    __half2 p0 = __floats2half2_rn(v.x, v.y);
    __half2 p1 = __floats2half2_rn(v.z, v.w);
    uint2 u;
    u.x = *reinterpret_cast<uint32_t*>(&p0);
    u.y = *reinterpret_cast<uint32_t*>(&p1);
    return u;
}

// ---------------------------------------------------------------------------
// Kernel 0: convert lora_A and lora_B to fp16.
// 1024 blocks x 256 threads; one float4 of each per thread (both are exactly
// 262144 float4s: 32*16*2048 and 32*2048*16).
// ---------------------------------------------------------------------------
__global__ __launch_bounds__(256) void convert_lora_kernel(
    const float* __restrict__ lora_A, const float* __restrict__ lora_B)
{
    const int idx = blockIdx.x * blockDim.x + threadIdx.x;
    *reinterpret_cast<uint2*>(&g_Ai[(size_t)idx * 4]) =
        f4_to_h4(reinterpret_cast<const float4*>(lora_A)[idx]);
    *reinterpret_cast<uint2*>(&g_Bi[(size_t)idx * 4]) =
        f4_to_h4(reinterpret_cast<const float4*>(lora_B)[idx]);
}

// ---------------------------------------------------------------------------
// Kernel 1 (merged): blocks [0, 8192) convert X (2M float4) and, for
// idx < 1M, W (1M float4 — W is 2048x2048, HALF the size of X; the missing
// guard here was the R6-R8 illegal-memory-access bug).
// Blocks [8192, 12288): LoRA shrink for token (bid-8192), fp16 data,
// fp32 accumulate.
// ---------------------------------------------------------------------------
__global__ __launch_bounds__(256) void prepass_kernel(
    const float* __restrict__ x, const float* __restrict__ w,
    const int* __restrict__ adapter_ids)
{
    const int bid = blockIdx.x;
    const int tid = threadIdx.x;

    if (bid < 8192) {
        const int idx = bid * 256 + tid;             // float4 index, < 2M
        *reinterpret_cast<uint2*>(&g_Xi[(size_t)idx * 4]) =
            f4_to_h4(reinterpret_cast<const float4*>(x)[idx]);
        if (idx < D_OUT * D_IN / 4) {                // W: only 1M float4!
            *reinterpret_cast<uint2*>(&g_Wi[(size_t)idx * 4]) =
                f4_to_h4(reinterpret_cast<const float4*>(w)[idx]);
        }
        return;
    }

    // ---- shrink: one block per token, 8 warps x 2 ranks ----
    __shared__ __align__(16) __half xsh[D_IN];
    const int n = bid - 8192;
    const float4* xg = reinterpret_cast<const float4*>(x + (size_t)n * D_IN);
    for (int i = tid; i < D_IN / 4; i += 256) {      // 512 float4
        *reinterpret_cast<uint2*>(&xsh[i * 4]) = f4_to_h4(xg[i]);
    }
    __syncthreads();

    const int a = adapter_ids[n];
    const int warp = tid >> 5, lane = tid & 31;
    const uint4* xs4 = reinterpret_cast<const uint4*>(xsh);   // 256 uint4

    #pragma unroll
    for (int rr = 0; rr < 2; rr++) {
        const int r = warp * 2 + rr;
        const uint4* Ar = reinterpret_cast<const uint4*>(
            g_Ai + ((size_t)a * RANK + r) * D_IN);
        float acc = 0.f;
        #pragma unroll
        for (int i = lane; i < 256; i += 32) {       // 8 iters
            uint4 av = __ldg(Ar + i);
            uint4 xv = xs4[i];
            float2 a0 = __half22float2(*reinterpret_cast<__half2*>(&av.x));
            float2 a1 = __half22float2(*reinterpret_cast<__half2*>(&av.y));
            float2 a2 = __half22float2(*reinterpret_cast<__half2*>(&av.z));
            float2 a3 = __half22float2(*reinterpret_cast<__half2*>(&av.w));
            float2 x0 = __half22float2(*reinterpret_cast<__half2*>(&xv.x));
            float2 x1 = __half22float2(*reinterpret_cast<__half2*>(&xv.y));
            float2 x2 = __half22float2(*reinterpret_cast<__half2*>(&xv.z));
            float2 x3 = __half22float2(*reinterpret_cast<__half2*>(&xv.w));
            acc += a0.x * x0.x + a0.y * x0.y + a1.x * x1.x + a1.y * x1.y
                 + a2.x * x2.x + a2.y * x2.y + a3.x * x3.x + a3.y * x3.y;
        }
        #pragma unroll
        for (int off = 16; off > 0; off >>= 1)
            acc += __shfl_down_sync(0xffffffffu, acc, off);
        if (lane == 0) g_Ares[(size_t)n * RANK + r] = acc;
    }
}

// ---------------------------------------------------------------------------
// Kernel 2: persistent fp16 mma.sync GEMM + fused LoRA expand epilogue.
// 304 CTAs (2/SM); deterministic static schedule t = bid, bid+304, ...
// 256 threads = 8 warps (2x4); warp tile 64x32; fp32 acc.
// ---------------------------------------------------------------------------
__global__ __launch_bounds__(TPB, 2) void gemm_mma_kernel(
    const int*   __restrict__ adapter_ids,
    const float* __restrict__ bias,
    const float* __restrict__ scaling,
    float*       __restrict__ out)
{
    extern __shared__ char dsm[];
    __shared__ __align__(16) float AresSh[BM][RANK];
    __shared__ int   adSh[BM];
    __shared__ float scSh[BM];

    const int tid  = threadIdx.x;
    const int wid  = tid >> 5, lane = tid & 31;
    const int warpM = wid >> 2;          // 0..1 (64 rows)
    const int warpN = wid & 3;           // 0..3 (32 cols)

    const uint32_t dynb = smem_u32(dsm);
    const uint32_t lmRow   = lane & 15;
    const uint32_t lmChunk = (lane >> 4) * 16;
    const uint32_t aByte = (warpM * 64 + lmRow) * ROW_STRIDE_B + lmChunk;
    const uint32_t bByte = (warpN * 32 + lmRow) * ROW_STRIDE_B + lmChunk;

    const int ldRow  = tid >> 2;           // rows 0..63
    const int ldCc   = (tid & 3) * 16;
    const int ldRow2 = ldRow + 64;

    for (unsigned int t = blockIdx.x; t < NTILES; t += gridDim.x) {
        // WAR guard: previous tile's epilogue reads of AresSh/adSh/scSh must
        // finish before this tile's preload overwrites them.
        __syncthreads();

        const int rowBlock = (int)(t >> 4) * BM;     // 32 row groups
        const int colBlock = (int)(t & 15) * BN;     // 16 col groups

        // epilogue data preload
        {
            const float4* ag  = reinterpret_cast<const float4*>(g_Ares + (size_t)rowBlock * RANK);
            float4*       as4 = reinterpret_cast<float4*>(&AresSh[0][0]);
            as4[tid]       = ag[tid];
            as4[tid + 256] = ag[tid + 256];
            if (tid < BM) {
                int a = adapter_ids[rowBlock + tid];
                adSh[tid] = a;
                scSh[tid] = scaling[a];
            }
        }

        const char* srcX = (const char*)(g_Xi + (size_t)rowBlock * D_IN);
        const char* srcW = (const char*)(g_Wi + (size_t)colBlock * D_IN);

        auto load_tile = [&](int kt, int stg) {
            const uint32_t sb = dynb + stg * STAGE_BYTES;
            const size_t koff = (size_t)kt * (BK * 2);
            const uint32_t d0 = ldRow * ROW_STRIDE_B + ldCc;
            const uint32_t d1 = ldRow2 * ROW_STRIDE_B + ldCc;
            const size_t s0 = (size_t)ldRow  * (D_IN * 2) + koff + ldCc;
            const size_t s1 = (size_t)ldRow2 * (D_IN * 2) + koff + ldCc;
            CP16(sb + 0 * ARR_BYTES + d0, srcX + s0);
            CP16(sb + 0 * ARR_BYTES + d1, srcX + s1);
            CP16(sb + 1 * ARR_BYTES + d0, srcW + s0);
            CP16(sb + 1 * ARR_BYTES + d1, srcW + s1);
            CP_COMMIT();
        };

        float acc[4][4][4];
        #pragma unroll
        for (int m = 0; m < 4; m++)
            #pragma unroll
            for (int n = 0; n < 4; n++)
                #pragma unroll
                for (int k = 0; k < 4; k++) acc[m][n][k] = 0.f;

        load_tile(0, 0);
        load_tile(1, 1);
        load_tile(2, 2);

        for (int kt = 0; kt < NKT; kt++) {
            const int stg = kt % STAGES;
            CP_WAIT(STAGES - 2);
            __syncthreads();
            if (kt + STAGES - 1 < NKT)
                load_tile(kt + STAGES - 1, (kt + STAGES - 1) % STAGES);
            else
                CP_COMMIT();   // empty group: keeps wait_group accounting exact

            const uint32_t sb = dynb + stg * STAGE_BYTES;
            const uint32_t aB = sb + 0 * ARR_BYTES + aByte;
            const uint32_t bB = sb + 1 * ARR_BYTES + bByte;

            #pragma unroll
            for (int s = 0; s < 2; s++) {          // two k16 steps per BK=32
                const uint32_t ko = s * 32;
                uint32_t ah[4][4], bh[2][4];
                #pragma unroll
                for (int m = 0; m < 4; m++)
                    ldsm4(ah[m], aB + m * 16 * ROW_STRIDE_B + ko);
                #pragma unroll
                for (int g = 0; g < 2; g++)
                    ldsm4(bh[g], bB + g * 16 * ROW_STRIDE_B + ko);
                #pragma unroll
                for (int m = 0; m < 4; m++)
                    #pragma unroll
                    for (int ng = 0; ng < 4; ng++) {
                        const int g = ng >> 1, sub = ng & 1;
                        mma_f16(acc[m][ng], ah[m], bh[g][sub], bh[g][sub + 2]);
                    }
            }
        }
        CP_WAIT(0);   // drain before next tile reuses stages

        // ---- epilogue: acc + bias + scale * (Ares . loraB_fp16[a, o, :]) ----
        const int gID = lane >> 2, tig = lane & 3;
        #pragma unroll
        for (int m = 0; m < 4; m++) {
            #pragma unroll
            for (int h = 0; h < 2; h++) {
                const int rl = warpM * 64 + m * 16 + gID + h * 8;
                const int n  = rowBlock + rl;
                const int a  = adSh[rl];
                const float sc = scSh[rl];
                const float* ar = &AresSh[rl][0];
                const float4 ar0 = *reinterpret_cast<const float4*>(ar + 0);
                const float4 ar1 = *reinterpret_cast<const float4*>(ar + 4);
                const float4 ar2 = *reinterpret_cast<const float4*>(ar + 8);
                const float4 ar3 = *reinterpret_cast<const float4*>(ar + 12);
                const __half* Bb = g_Bi + (size_t)a * D_OUT * RANK;
                float* orow = out + (size_t)n * D_OUT + colBlock;

                #pragma unroll
                for (int ng = 0; ng < 4; ng++) {
                    const int c0 = warpN * 32 + ng * 8 + 2 * tig;
                    float r2[2];
                    #pragma unroll
                    for (int q = 0; q < 2; q++) {
                        const int o = colBlock + c0 + q;
                        const uint4* Bp = reinterpret_cast<const uint4*>(Bb + (size_t)o * RANK);
                        uint4 u0 = __ldg(Bp);        // halves 0..7
                        uint4 u1 = __ldg(Bp + 1);    // halves 8..15
                        float sdot = 0.f;
                        sdot = dot_h2(sdot, u0.x, ar0.x, ar0.y);
                        sdot = dot_h2(sdot, u0.y, ar0.z, ar0.w);
                        sdot = dot_h2(sdot, u0.z, ar1.x, ar1.y);
                        sdot = dot_h2(sdot, u0.w, ar1.z, ar1.w);
                        sdot = dot_h2(sdot, u1.x, ar2.x, ar2.y);
                        sdot = dot_h2(sdot, u1.y, ar2.z, ar2.w);
                        sdot = dot_h2(sdot, u1.z, ar3.x, ar3.y);
                        sdot = dot_h2(sdot, u1.w, ar3.z, ar3.w);
                        r2[q] = acc[m][ng][h * 2 + q] + __ldg(bias + o) + sc * sdot;
                    }
                    *reinterpret_cast<float2*>(orow + c0) = make_float2(r2[0], r2[1]);
                }
            }
        }
    }
}

// ---------------------------------------------------------------------------
// Launch
// ---------------------------------------------------------------------------
extern "C" void kernel_launch(void* const* d_in, const int* in_sizes, int n_in,
                              void* d_out, int out_size)
{
    const float* x           = (const float*)d_in[0];
    const int*   adapter_ids = (const int*)  d_in[1];
    const float* W_base      = (const float*)d_in[2];
    const float* b_base      = (const float*)d_in[3];
    const float* lora_A      = (const float*)d_in[4];
    const float* lora_B      = (const float*)d_in[5];
    const float* lora_scal   = (const float*)d_in[6];
    float*       out         = (float*)d_out;

    cudaFuncSetAttribute(gemm_mma_kernel,
                         cudaFuncAttributeMaxDynamicSharedMemorySize, DYN_BYTES);

    convert_lora_kernel<<<1024, 256>>>(lora_A, lora_B);
    prepass_kernel<<<8192 + N_TOK, 256>>>(x, W_base, adapter_ids);
    gemm_mma_kernel<<<GRID_PERSIST, TPB, DYN_BYTES>>>(adapter_ids, b_base,
                                                      lora_scal, out);
}

// round 10
// speedup vs baseline: 5.8508x; 1.1183x over previous
#include <cuda_runtime.h>
#include <cuda_fp16.h>
#include <cstdint>

// ---------------- problem constants ----------------
#define N_TOK 4096
#define D_IN  2048
#define D_OUT 2048
#define RANK  16
#define MAX_LORAS 32

// ---------------- GEMM tiling ----------------
#define BM 128
#define BN 128
#define BK 64                 // fp16 elems per K-tile (128 bytes/row)
#define NKT (D_IN / BK)       // 32
#define TPB 256
#define STAGES 3
#define NTILES ((N_TOK / BM) * (D_OUT / BN))   // 512
#define GRID_PERSIST 304      // 2 CTAs/SM x 152 SMs (GB300)

#define ARR_BYTES (128 * 128)            // 16384 per tile array (128 rows x 128B)
#define STAGE_BYTES (2 * ARR_BYTES)      // A, B  (32768)
#define DYN_BYTES (STAGES * STAGE_BYTES) // 98304 -> 2 CTAs/SM

// XOR-SW128 swizzle: byte addr = row*128 + (col ^ ((row&7)<<4)), col in [0,128)
#define SWADDR(row, col) ((uint32_t)((row) * 128 + ((col) ^ (((row) & 7) << 4))))

// ---------------- device scratch (no runtime allocation allowed) ----------------
__device__ __align__(16) float  g_Ares[N_TOK * RANK];
__device__ __align__(16) __half g_Xi[N_TOK * D_IN];
__device__ __align__(16) __half g_Wi[D_OUT * D_IN];
__device__ __align__(16) __half g_Ai[MAX_LORAS * RANK * D_IN];
__device__ __align__(16) __half g_Bi[MAX_LORAS * D_OUT * RANK];

// ---------------- PTX helpers (baseline-portable: sm_80-era ops) ----------------
__device__ __forceinline__ uint32_t smem_u32(const void* p) {
    uint32_t a;
    asm("{ .reg .u64 t; cvta.to.shared.u64 t, %1; cvt.u32.u64 %0, t; }" : "=r"(a) : "l"(p));
    return a;
}
#define CP16(dst, src) \
    asm volatile("cp.async.cg.shared.global [%0], [%1], 16;" :: "r"(dst), "l"(src) : "memory")
#define CP_COMMIT()  asm volatile("cp.async.commit_group;" ::: "memory")
#define CP_WAIT(n)   asm volatile("cp.async.wait_group %0;" :: "n"(n) : "memory")

__device__ __forceinline__ void ldsm4(uint32_t* r, uint32_t addr) {
    asm volatile("ldmatrix.sync.aligned.m8n8.x4.shared.b16 {%0,%1,%2,%3}, [%4];"
        : "=r"(r[0]), "=r"(r[1]), "=r"(r[2]), "=r"(r[3]) : "r"(addr));
}
__device__ __forceinline__ void mma_f16(float* d, const uint32_t* a,
                                        uint32_t b0, uint32_t b1) {
    asm volatile(
        "mma.sync.aligned.m16n8k16.row.col.f32.f16.f16.f32 "
        "{%0,%1,%2,%3}, {%4,%5,%6,%7}, {%8,%9}, {%0,%1,%2,%3};"
        : "+f"(d[0]), "+f"(d[1]), "+f"(d[2]), "+f"(d[3])
        : "r"(a[0]), "r"(a[1]), "r"(a[2]), "r"(a[3]), "r"(b0), "r"(b1));
}
__device__ __forceinline__ float dot_h2(float acc, uint32_t h2, float a0, float a1) {
    float2 f = __half22float2(*reinterpret_cast<__half2*>(&h2));
    return acc + a0 * f.x + a1 * f.y;
}
__device__ __forceinline__ uint2 f4_to_h4(float4 v) {
    __half2 p0 = __floats2half2_rn(v.x, v.y);
    __half2 p1 = __floats2half2_rn(v.z, v.w);
    uint2 u;
    u.x = *reinterpret_cast<uint32_t*>(&p0);
    u.y = *reinterpret_cast<uint32_t*>(&p1);
    return u;
}

// ---------------------------------------------------------------------------
// Kernel 0: convert lora_A and lora_B to fp16 (each exactly 262144 float4).
// ---------------------------------------------------------------------------
__global__ __launch_bounds__(256) void convert_lora_kernel(
    const float* __restrict__ lora_A, const float* __restrict__ lora_B)
{
    const int idx = blockIdx.x * blockDim.x + threadIdx.x;
    *reinterpret_cast<uint2*>(&g_Ai[(size_t)idx * 4]) =
        f4_to_h4(reinterpret_cast<const float4*>(lora_A)[idx]);
    *reinterpret_cast<uint2*>(&g_Bi[(size_t)idx * 4]) =
        f4_to_h4(reinterpret_cast<const float4*>(lora_B)[idx]);
}

// ---------------------------------------------------------------------------
// Kernel 1 (merged): blocks [0, 8192) convert X (2M float4) and W for
// idx < 1M (W is 2048x2048 = HALF of X — guard is load-bearing).
// Blocks [8192, 12288): LoRA shrink for token (bid-8192), fp16, fp32 acc.
// ---------------------------------------------------------------------------
__global__ __launch_bounds__(256) void prepass_kernel(
    const float* __restrict__ x, const float* __restrict__ w,
    const int* __restrict__ adapter_ids)
{
    const int bid = blockIdx.x;
    const int tid = threadIdx.x;

    if (bid < 8192) {
        const int idx = bid * 256 + tid;             // float4 index, < 2M
        *reinterpret_cast<uint2*>(&g_Xi[(size_t)idx * 4]) =
            f4_to_h4(reinterpret_cast<const float4*>(x)[idx]);
        if (idx < D_OUT * D_IN / 4) {                // W: only 1M float4
            *reinterpret_cast<uint2*>(&g_Wi[(size_t)idx * 4]) =
                f4_to_h4(reinterpret_cast<const float4*>(w)[idx]);
        }
        return;
    }

    // ---- shrink: one block per token, 8 warps x 2 ranks ----
    __shared__ __align__(16) __half xsh[D_IN];
    const int n = bid - 8192;
    const float4* xg = reinterpret_cast<const float4*>(x + (size_t)n * D_IN);
    for (int i = tid; i < D_IN / 4; i += 256) {
        *reinterpret_cast<uint2*>(&xsh[i * 4]) = f4_to_h4(xg[i]);
    }
    __syncthreads();

    const int a = adapter_ids[n];
    const int warp = tid >> 5, lane = tid & 31;
    const uint4* xs4 = reinterpret_cast<const uint4*>(xsh);   // 256 uint4

    #pragma unroll
    for (int rr = 0; rr < 2; rr++) {
        const int r = warp * 2 + rr;
        const uint4* Ar = reinterpret_cast<const uint4*>(
            g_Ai + ((size_t)a * RANK + r) * D_IN);
        float acc = 0.f;
        #pragma unroll
        for (int i = lane; i < 256; i += 32) {
            uint4 av = __ldg(Ar + i);
            uint4 xv = xs4[i];
            float2 a0 = __half22float2(*reinterpret_cast<__half2*>(&av.x));
            float2 a1 = __half22float2(*reinterpret_cast<__half2*>(&av.y));
            float2 a2 = __half22float2(*reinterpret_cast<__half2*>(&av.z));
            float2 a3 = __half22float2(*reinterpret_cast<__half2*>(&av.w));
            float2 x0 = __half22float2(*reinterpret_cast<__half2*>(&xv.x));
            float2 x1 = __half22float2(*reinterpret_cast<__half2*>(&xv.y));
            float2 x2 = __half22float2(*reinterpret_cast<__half2*>(&xv.z));
            float2 x3 = __half22float2(*reinterpret_cast<__half2*>(&xv.w));
            acc += a0.x * x0.x + a0.y * x0.y + a1.x * x1.x + a1.y * x1.y
                 + a2.x * x2.x + a2.y * x2.y + a3.x * x3.x + a3.y * x3.y;
        }
        #pragma unroll
        for (int off = 16; off > 0; off >>= 1)
            acc += __shfl_down_sync(0xffffffffu, acc, off);
        if (lane == 0) g_Ares[(size_t)n * RANK + r] = acc;
    }
}

// ---------------------------------------------------------------------------
// Kernel 2: persistent fp16 mma.sync GEMM + fused LoRA expand epilogue.
// BK=64 (4 k16 steps per barrier), 3 stages, XOR-SW128 smem layout.
// 304 CTAs (2/SM), static schedule. 8 warps (2x4), warp tile 64x32, fp32 acc.
// ---------------------------------------------------------------------------
__global__ __launch_bounds__(TPB, 2) void gemm_mma_kernel(
    const int*   __restrict__ adapter_ids,
    const float* __restrict__ bias,
    const float* __restrict__ scaling,
    float*       __restrict__ out)
{
    extern __shared__ char dsm[];
    __shared__ __align__(16) float AresSh[BM][RANK];
    __shared__ int   adSh[BM];
    __shared__ float scSh[BM];

    const int tid  = threadIdx.x;
    const int wid  = tid >> 5, lane = tid & 31;
    const int warpM = wid >> 2;          // 0..1 (64 rows)
    const int warpN = wid & 3;           // 0..3 (32 cols)

    const uint32_t dynb = smem_u32(dsm);

    // ldmatrix per-thread row/col within the tile arrays
    const int lmRow   = lane & 15;
    const int lmChunk = (lane >> 4) * 16;
    const int aRow0 = warpM * 64 + lmRow;
    const int bRow0 = warpN * 32 + lmRow;

    // cp.async mapping: 1024 16B-chunks per array, 4 per thread per array
    // chunk c: row = c>>3, col = (c&7)*16
    const int ldCol = (tid & 7) * 16;

    for (unsigned int t = blockIdx.x; t < NTILES; t += gridDim.x) {
        // WAR guard: prior tile's epilogue reads of AresSh/adSh/scSh
        __syncthreads();

        const int rowBlock = (int)(t >> 4) * BM;     // 32 row groups
        const int colBlock = (int)(t & 15) * BN;     // 16 col groups

        // epilogue data preload
        {
            const float4* ag  = reinterpret_cast<const float4*>(g_Ares + (size_t)rowBlock * RANK);
            float4*       as4 = reinterpret_cast<float4*>(&AresSh[0][0]);
            as4[tid]       = ag[tid];
            as4[tid + 256] = ag[tid + 256];
            if (tid < BM) {
                int a = adapter_ids[rowBlock + tid];
                adSh[tid] = a;
                scSh[tid] = scaling[a];
            }
        }

        const char* srcX = (const char*)(g_Xi + (size_t)rowBlock * D_IN);
        const char* srcW = (const char*)(g_Wi + (size_t)colBlock * D_IN);

        auto load_tile = [&](int kt, int stg) {
            const uint32_t sb = dynb + stg * STAGE_BYTES;
            const size_t koff = (size_t)kt * (BK * 2);   // 128 bytes per row
            #pragma unroll
            for (int i = 0; i < 4; i++) {
                const int c   = tid + i * 256;           // 0..1023
                const int row = c >> 3;
                const uint32_t d = SWADDR(row, ldCol);
                const size_t  s = (size_t)row * (D_IN * 2) + koff + ldCol;
                CP16(sb + 0 * ARR_BYTES + d, srcX + s);
                CP16(sb + 1 * ARR_BYTES + d, srcW + s);
            }
            CP_COMMIT();
        };

        float acc[4][4][4];
        #pragma unroll
        for (int m = 0; m < 4; m++)
            #pragma unroll
            for (int n = 0; n < 4; n++)
                #pragma unroll
                for (int k = 0; k < 4; k++) acc[m][n][k] = 0.f;

        load_tile(0, 0);
        load_tile(1, 1);

        for (int kt = 0; kt < NKT; kt++) {
            const int stg = kt % STAGES;
            CP_WAIT(STAGES - 2);
            __syncthreads();
            if (kt + STAGES - 1 < NKT)
                load_tile(kt + STAGES - 1, (kt + STAGES - 1) % STAGES);
            else
                CP_COMMIT();   // empty group keeps wait accounting exact

            const uint32_t sb = dynb + stg * STAGE_BYTES;
            const uint32_t aArr = sb + 0 * ARR_BYTES;
            const uint32_t bArr = sb + 1 * ARR_BYTES;

            #pragma unroll
            for (int s = 0; s < 4; s++) {          // four k16 steps per BK=64
                const int ko = s * 32;             // 16 fp16 = 32 bytes
                uint32_t ah[4][4], bh[2][4];
                #pragma unroll
                for (int m = 0; m < 4; m++)
                    ldsm4(ah[m], aArr + SWADDR(aRow0 + m * 16, ko + lmChunk));
                #pragma unroll
                for (int g = 0; g < 2; g++)
                    ldsm4(bh[g], bArr + SWADDR(bRow0 + g * 16, ko + lmChunk));
                #pragma unroll
                for (int m = 0; m < 4; m++)
                    #pragma unroll
                    for (int ng = 0; ng < 4; ng++) {
                        const int g = ng >> 1, sub = ng & 1;
                        mma_f16(acc[m][ng], ah[m], bh[g][sub], bh[g][sub + 2]);
                    }
            }
        }
        CP_WAIT(0);   // drain before next tile reuses stages

        // ---- epilogue: acc + bias + scale * (Ares . loraB_fp16[a, o, :]) ----
        const int gID = lane >> 2, tig = lane & 3;
        #pragma unroll
        for (int m = 0; m < 4; m++) {
            #pragma unroll
            for (int h = 0; h < 2; h++) {
                const int rl = warpM * 64 + m * 16 + gID + h * 8;
                const int n  = rowBlock + rl;
                const int a  = adSh[rl];
                const float sc = scSh[rl];
                const float* ar = &AresSh[rl][0];
                const float4 ar0 = *reinterpret_cast<const float4*>(ar + 0);
                const float4 ar1 = *reinterpret_cast<const float4*>(ar + 4);
                const float4 ar2 = *reinterpret_cast<const float4*>(ar + 8);
                const float4 ar3 = *reinterpret_cast<const float4*>(ar + 12);
                const __half* Bb = g_Bi + (size_t)a * D_OUT * RANK;
                float* orow = out + (size_t)n * D_OUT + colBlock;

                #pragma unroll
                for (int ng = 0; ng < 4; ng++) {
                    const int c0 = warpN * 32 + ng * 8 + 2 * tig;
                    float r2[2];
                    #pragma unroll
                    for (int q = 0; q < 2; q++) {
                        const int o = colBlock + c0 + q;
                        const uint4* Bp = reinterpret_cast<const uint4*>(Bb + (size_t)o * RANK);
                        uint4 u0 = __ldg(Bp);
                        uint4 u1 = __ldg(Bp + 1);
                        float sdot = 0.f;
                        sdot = dot_h2(sdot, u0.x, ar0.x, ar0.y);
                        sdot = dot_h2(sdot, u0.y, ar0.z, ar0.w);
                        sdot = dot_h2(sdot, u0.z, ar1.x, ar1.y);
                        sdot = dot_h2(sdot, u0.w, ar1.z, ar1.w);
                        sdot = dot_h2(sdot, u1.x, ar2.x, ar2.y);
                        sdot = dot_h2(sdot, u1.y, ar2.z, ar2.w);
                        sdot = dot_h2(sdot, u1.z, ar3.x, ar3.y);
                        sdot = dot_h2(sdot, u1.w, ar3.z, ar3.w);
                        r2[q] = acc[m][ng][h * 2 + q] + __ldg(bias + o) + sc * sdot;
                    }
                    *reinterpret_cast<float2*>(orow + c0) = make_float2(r2[0], r2[1]);
                }
            }
        }
    }
}

// ---------------------------------------------------------------------------
// Launch
// ---------------------------------------------------------------------------
extern "C" void kernel_launch(void* const* d_in, const int* in_sizes, int n_in,
                              void* d_out, int out_size)
{
    const float* x           = (const float*)d_in[0];
    const int*   adapter_ids = (const int*)  d_in[1];
    const float* W_base      = (const float*)d_in[2];
    const float* b_base      = (const float*)d_in[3];
    const float* lora_A      = (const float*)d_in[4];
    const float* lora_B      = (const float*)d_in[5];
    const float* lora_scal   = (const float*)d_in[6];
    float*       out         = (float*)d_out;

    cudaFuncSetAttribute(gemm_mma_kernel,
                         cudaFuncAttributeMaxDynamicSharedMemorySize, DYN_BYTES);

    convert_lora_kernel<<<1024, 256>>>(lora_A, lora_B);
    prepass_kernel<<<8192 + N_TOK, 256>>>(x, W_base, adapter_ids);
    gemm_mma_kernel<<<GRID_PERSIST, TPB, DYN_BYTES>>>(adapter_ids, b_base,
                                                      lora_scal, out);
}

// round 11
// speedup vs baseline: 6.5276x; 1.1157x over previous
#include <cuda_runtime.h>
#include <cuda_fp16.h>
#include <cstdint>

// ---------------- problem constants ----------------
#define N_TOK 4096
#define D_IN  2048
#define D_OUT 2048
#define RANK  16
#define MAX_LORAS 32

// ---------------- GEMM tiling ----------------
#define BM 128
#define BN 128
#define BK 64                 // fp16 elems per K-tile (128 bytes/row)
#define NKT (D_IN / BK)       // 32
#define TPB 256
#define STAGES 3
#define NTILES ((N_TOK / BM) * (D_OUT / BN))   // 512
#define GRID_PERSIST 304      // 2 CTAs/SM x 152 SMs (GB300)

#define ARR_BYTES (128 * 128)            // 16384 per tile array
#define STAGE_BYTES (2 * ARR_BYTES)      // A, B  (32768)
#define DYN_BYTES (STAGES * STAGE_BYTES) // 98304 -> 2 CTAs/SM

// XOR-SW128 swizzle: byte addr = row*128 + (col ^ ((row&7)<<4)), col in [0,128)
#define SWADDR(row, col) ((uint32_t)((row) * 128 + ((col) ^ (((row) & 7) << 4))))

// ---------------- device scratch (no runtime allocation allowed) ----------------
__device__ __align__(16) float  g_Ares[N_TOK * RANK];     // SORTED token order
__device__ __align__(16) __half g_Xi[N_TOK * D_IN];
__device__ __align__(16) __half g_Wi[D_OUT * D_IN];
__device__ __align__(16) __half g_Ai[MAX_LORAS * RANK * D_IN];
__device__ __align__(16) __half g_Bi[MAX_LORAS * D_OUT * RANK];
__device__ __align__(16) int    g_perm[N_TOK];            // sorted pos -> token
__device__ __align__(16) int    g_sortedAdp[N_TOK];       // sorted pos -> adapter
__device__ __align__(16) int    g_binStart[MAX_LORAS + 1];

// ---------------- PTX helpers (baseline-portable: sm_80-era ops) ----------------
__device__ __forceinline__ uint32_t smem_u32(const void* p) {
    uint32_t a;
    asm("{ .reg .u64 t; cvta.to.shared.u64 t, %1; cvt.u32.u64 %0, t; }" : "=r"(a) : "l"(p));
    return a;
}
#define CP16(dst, src) \
    asm volatile("cp.async.cg.shared.global [%0], [%1], 16;" :: "r"(dst), "l"(src) : "memory")
#define CP_COMMIT()  asm volatile("cp.async.commit_group;" ::: "memory")
#define CP_WAIT(n)   asm volatile("cp.async.wait_group %0;" :: "n"(n) : "memory")

__device__ __forceinline__ void ldsm4(uint32_t* r, uint32_t addr) {
    asm volatile("ldmatrix.sync.aligned.m8n8.x4.shared.b16 {%0,%1,%2,%3}, [%4];"
        : "=r"(r[0]), "=r"(r[1]), "=r"(r[2]), "=r"(r[3]) : "r"(addr));
}
__device__ __forceinline__ void mma_f16(float* d, const uint32_t* a,
                                        uint32_t b0, uint32_t b1) {
    asm volatile(
        "mma.sync.aligned.m16n8k16.row.col.f32.f16.f16.f32 "
        "{%0,%1,%2,%3}, {%4,%5,%6,%7}, {%8,%9}, {%0,%1,%2,%3};"
        : "+f"(d[0]), "+f"(d[1]), "+f"(d[2]), "+f"(d[3])
        : "r"(a[0]), "r"(a[1]), "r"(a[2]), "r"(a[3]), "r"(b0), "r"(b1));
}
__device__ __forceinline__ float dot_h2(float acc, uint32_t h2, float a0, float a1) {
    float2 f = __half22float2(*reinterpret_cast<__half2*>(&h2));
    return acc + a0 * f.x + a1 * f.y;
}
__device__ __forceinline__ uint2 f4_to_h4(float4 v) {
    __half2 p0 = __floats2half2_rn(v.x, v.y);
    __half2 p1 = __floats2half2_rn(v.z, v.w);
    uint2 u;
    u.x = *reinterpret_cast<uint32_t*>(&p0);
    u.y = *reinterpret_cast<uint32_t*>(&p1);
    return u;
}

// ---------------------------------------------------------------------------
// Kernel 1 (prepass): blocks [0,8192) convert X (2M float4) + W (1M float4,
// guard load-bearing); blocks [8192,9216) convert lora_A/lora_B (1M float4
// each); block 9216 = single-block deterministic stable counting sort of
// tokens by adapter. All parts independent.
// ---------------------------------------------------------------------------
__global__ __launch_bounds__(256) void prepass_kernel(
    const float* __restrict__ x, const float* __restrict__ w,
    const float* __restrict__ lora_A, const float* __restrict__ lora_B,
    const int* __restrict__ adapter_ids)
{
    const int bid = blockIdx.x;
    const int tid = threadIdx.x;

    if (bid < 8192) {
        const int idx = bid * 256 + tid;             // float4 index, < 2M
        *reinterpret_cast<uint2*>(&g_Xi[(size_t)idx * 4]) =
            f4_to_h4(reinterpret_cast<const float4*>(x)[idx]);
        if (idx < D_OUT * D_IN / 4) {                // W: only 1M float4
            *reinterpret_cast<uint2*>(&g_Wi[(size_t)idx * 4]) =
                f4_to_h4(reinterpret_cast<const float4*>(w)[idx]);
        }
        return;
    }
    if (bid < 9216) {
        const int idx = (bid - 8192) * 256 + tid;    // < 262144
        *reinterpret_cast<uint2*>(&g_Ai[(size_t)idx * 4]) =
            f4_to_h4(reinterpret_cast<const float4*>(lora_A)[idx]);
        *reinterpret_cast<uint2*>(&g_Bi[(size_t)idx * 4]) =
            f4_to_h4(reinterpret_cast<const float4*>(lora_B)[idx]);
        return;
    }

    // ---- sort block: stable counting sort of 4096 tokens into 32 bins ----
    __shared__ uint32_t hist[256 * 33];   // padded row stride 33 (bank spread)
    __shared__ uint32_t binTotal[32];
    __shared__ uint32_t binBase[33];

    int ids[16];
    #pragma unroll
    for (int j = 0; j < 33; j++) hist[tid * 33 + j] = 0;
    __syncthreads();
    #pragma unroll
    for (int j = 0; j < 16; j++) {
        ids[j] = adapter_ids[tid * 16 + j];
        hist[tid * 33 + ids[j]]++;
    }
    __syncthreads();
    if (tid < 32) {        // per-bin prefix over threads (stable base)
        uint32_t s = 0;
        for (int t = 0; t < 256; t++) {
            uint32_t c = hist[t * 33 + tid];
            hist[t * 33 + tid] = s;
            s += c;
        }
        binTotal[tid] = s;
    }
    __syncthreads();
    if (tid == 0) {
        uint32_t acc = 0;
        for (int b = 0; b < 32; b++) { binBase[b] = acc; acc += binTotal[b]; }
        binBase[32] = acc;   // = 4096
    }
    __syncthreads();
    #pragma unroll
    for (int j = 0; j < 16; j++) {       // stable scatter
        const int b = ids[j];
        const uint32_t off = hist[tid * 33 + b]++;
        const uint32_t pos = binBase[b] + off;
        g_perm[pos]      = tid * 16 + j;
        g_sortedAdp[pos] = b;
    }
    if (tid < 33) g_binStart[tid] = (int)binBase[tid];
}

// ---------------------------------------------------------------------------
// Kernel 2: shrink as per-adapter mma GEMM.
// Block (a, c): Ares[sorted base+r, :] = X[tok_r, :] . A[a]^T for up to 128
// tokens of adapter a. 8 warps, warp = one m16 fragment (16 tokens) x n16.
// ---------------------------------------------------------------------------
__global__ __launch_bounds__(256) void shrink_gemm_kernel()
{
    __shared__ __align__(16) char xs[2][16384];   // X tiles 128x64 fp16
    __shared__ __align__(16) char as_[2][2048];   // A tiles 16x64 fp16
    __shared__ int tokSh[128];

    const int a   = blockIdx.x;
    const int cy  = blockIdx.y;
    const int tid = threadIdx.x;
    const int wid = tid >> 5, lane = tid & 31;

    const int binS = g_binStart[a], binE = g_binStart[a + 1];
    const int base = binS + cy * 128;
    int cnt = binE - base;
    if (cnt <= 0) return;
    if (cnt > 128) cnt = 128;

    if (tid < 128) tokSh[tid] = g_perm[base + (tid < cnt ? tid : cnt - 1)];
    __syncthreads();

    const int ldCol = (tid & 7) * 16;
    auto load = [&](int kt, int stg) {
        #pragma unroll
        for (int i = 0; i < 4; i++) {
            const int c = tid + i * 256;          // 0..1023
            const int row = c >> 3;
            CP16(smem_u32(xs[stg]) + SWADDR(row, ldCol),
                 (const char*)g_Xi + (size_t)tokSh[row] * 4096 + kt * 128 + ldCol);
        }
        if (tid < 128) {
            const int row = tid >> 3;             // 0..15
            CP16(smem_u32(as_[stg]) + SWADDR(row, ldCol),
                 (const char*)g_Ai + ((size_t)a * RANK + row) * 4096 + kt * 128 + ldCol);
        }
        CP_COMMIT();
    };

    float acc2[2][4];
    #pragma unroll
    for (int i = 0; i < 2; i++)
        #pragma unroll
        for (int k = 0; k < 4; k++) acc2[i][k] = 0.f;

    const int lmRow = lane & 15, lmChunk = (lane >> 4) * 16;

    load(0, 0);
    for (int kt = 0; kt < NKT; kt++) {
        if (kt + 1 < NKT) load(kt + 1, (kt + 1) & 1); else CP_COMMIT();
        CP_WAIT(1);
        __syncthreads();
        const uint32_t xb = smem_u32(xs[kt & 1]);
        const uint32_t ab = smem_u32(as_[kt & 1]);
        #pragma unroll
        for (int s = 0; s < 4; s++) {
            uint32_t xh[4], bh[4];
            ldsm4(xh, xb + SWADDR(wid * 16 + lmRow, s * 32 + lmChunk));
            ldsm4(bh, ab + SWADDR(lmRow,           s * 32 + lmChunk));
            mma_f16(acc2[0], xh, bh[0], bh[2]);
            mma_f16(acc2[1], xh, bh[1], bh[3]);
        }
        __syncthreads();   // protect stage (kt+1)&1 reuse next iteration
    }

    const int gID = lane >> 2, tig = lane & 3;
    #pragma unroll
    for (int h = 0; h < 2; h++) {
        const int r = wid * 16 + gID + h * 8;
        if (r < cnt) {
            float* dst = g_Ares + (size_t)(base + r) * RANK;
            #pragma unroll
            for (int ng = 0; ng < 2; ng++) {
                const int c = ng * 8 + 2 * tig;
                *reinterpret_cast<float2*>(dst + c) =
                    make_float2(acc2[ng][h * 2], acc2[ng][h * 2 + 1]);
            }
        }
    }
}

// ---------------------------------------------------------------------------
// Kernel 3: persistent fp16 mma.sync GEMM over SORTED token rows + fused
// LoRA expand epilogue (adapter-uniform rows -> L1-cached g_Bi reads).
// ---------------------------------------------------------------------------
__global__ __launch_bounds__(TPB, 2) void gemm_mma_kernel(
    const float* __restrict__ bias,
    const float* __restrict__ scaling,
    float*       __restrict__ out)
{
    extern __shared__ char dsm[];
    __shared__ __align__(16) float AresSh[BM][RANK];
    __shared__ int   adSh[BM];
    __shared__ float scSh[BM];
    __shared__ int   tokSh[BM];

    const int tid  = threadIdx.x;
    const int wid  = tid >> 5, lane = tid & 31;
    const int warpM = wid >> 2;          // 0..1 (64 rows)
    const int warpN = wid & 3;           // 0..3 (32 cols)

    const uint32_t dynb = smem_u32(dsm);
    const int lmRow   = lane & 15;
    const int lmChunk = (lane >> 4) * 16;
    const int aRow0 = warpM * 64 + lmRow;
    const int bRow0 = warpN * 32 + lmRow;
    const int ldCol = (tid & 7) * 16;

    for (unsigned int t = blockIdx.x; t < NTILES; t += gridDim.x) {
        // WAR guard: prior tile's epilogue reads of smem preload arrays
        __syncthreads();

        const int rowBlock = (int)(t >> 4) * BM;     // sorted-row block
        const int colBlock = (int)(t & 15) * BN;

        // preload: Ares rows (sorted-contiguous), adapters, scales, tokens
        {
            const float4* ag  = reinterpret_cast<const float4*>(g_Ares + (size_t)rowBlock * RANK);
            float4*       as4 = reinterpret_cast<float4*>(&AresSh[0][0]);
            as4[tid]       = ag[tid];
            as4[tid + 256] = ag[tid + 256];
            if (tid < BM) {
                const int sp = rowBlock + tid;
                const int a  = g_sortedAdp[sp];
                adSh[tid]  = a;
                scSh[tid]  = scaling[a];
                tokSh[tid] = g_perm[sp];
            }
        }
        __syncthreads();   // tokSh ready before gathered loads

        const char* srcW = (const char*)(g_Wi + (size_t)colBlock * D_IN);

        auto load_tile = [&](int kt, int stg) {
            const uint32_t sb = dynb + stg * STAGE_BYTES;
            const size_t koff = (size_t)kt * (BK * 2);   // 128 B per row
            #pragma unroll
            for (int i = 0; i < 4; i++) {
                const int c   = tid + i * 256;           // 0..1023
                const int row = c >> 3;
                const uint32_t d = SWADDR(row, ldCol);
                CP16(sb + 0 * ARR_BYTES + d,
                     (const char*)g_Xi + (size_t)tokSh[row] * (D_IN * 2) + koff + ldCol);
                CP16(sb + 1 * ARR_BYTES + d,
                     srcW + (size_t)row * (D_IN * 2) + koff + ldCol);
            }
            CP_COMMIT();
        };

        float acc[4][4][4];
        #pragma unroll
        for (int m = 0; m < 4; m++)
            #pragma unroll
            for (int n = 0; n < 4; n++)
                #pragma unroll
                for (int k = 0; k < 4; k++) acc[m][n][k] = 0.f;

        load_tile(0, 0);
        load_tile(1, 1);

        for (int kt = 0; kt < NKT; kt++) {
            const int stg = kt % STAGES;
            CP_WAIT(STAGES - 2);
            __syncthreads();
            if (kt + STAGES - 1 < NKT)
                load_tile(kt + STAGES - 1, (kt + STAGES - 1) % STAGES);
            else
                CP_COMMIT();   // empty group keeps wait accounting exact

            const uint32_t sb = dynb + stg * STAGE_BYTES;
            const uint32_t aArr = sb + 0 * ARR_BYTES;
            const uint32_t bArr = sb + 1 * ARR_BYTES;

            #pragma unroll
            for (int s = 0; s < 4; s++) {
                const int ko = s * 32;
                uint32_t ah[4][4], bh[2][4];
                #pragma unroll
                for (int m = 0; m < 4; m++)
                    ldsm4(ah[m], aArr + SWADDR(aRow0 + m * 16, ko + lmChunk));
                #pragma unroll
                for (int g = 0; g < 2; g++)
                    ldsm4(bh[g], bArr + SWADDR(bRow0 + g * 16, ko + lmChunk));
                #pragma unroll
                for (int m = 0; m < 4; m++)
                    #pragma unroll
                    for (int ng = 0; ng < 4; ng++) {
                        const int g = ng >> 1, sub = ng & 1;
                        mma_f16(acc[m][ng], ah[m], bh[g][sub], bh[g][sub + 2]);
                    }
            }
        }
        CP_WAIT(0);   // drain before next tile reuses stages

        // ---- epilogue: acc + bias + scale * (Ares . loraB_fp16[a, o, :]) ----
        const int gID = lane >> 2, tig = lane & 3;
        #pragma unroll
        for (int m = 0; m < 4; m++) {
            #pragma unroll
            for (int h = 0; h < 2; h++) {
                const int rl = warpM * 64 + m * 16 + gID + h * 8;
                const int tok = tokSh[rl];
                const int a   = adSh[rl];
                const float sc = scSh[rl];
                const float* ar = &AresSh[rl][0];
                const float4 ar0 = *reinterpret_cast<const float4*>(ar + 0);
                const float4 ar1 = *reinterpret_cast<const float4*>(ar + 4);
                const float4 ar2 = *reinterpret_cast<const float4*>(ar + 8);
                const float4 ar3 = *reinterpret_cast<const float4*>(ar + 12);
                const __half* Bb = g_Bi + (size_t)a * D_OUT * RANK;
                float* orow = out + (size_t)tok * D_OUT + colBlock;

                #pragma unroll
                for (int ng = 0; ng < 4; ng++) {
                    const int c0 = warpN * 32 + ng * 8 + 2 * tig;
                    float r2[2];
                    #pragma unroll
                    for (int q = 0; q < 2; q++) {
                        const int o = colBlock + c0 + q;
                        const uint4* Bp = reinterpret_cast<const uint4*>(Bb + (size_t)o * RANK);
                        uint4 u0 = __ldg(Bp);
                        uint4 u1 = __ldg(Bp + 1);
                        float sdot = 0.f;
                        sdot = dot_h2(sdot, u0.x, ar0.x, ar0.y);
                        sdot = dot_h2(sdot, u0.y, ar0.z, ar0.w);
                        sdot = dot_h2(sdot, u0.z, ar1.x, ar1.y);
                        sdot = dot_h2(sdot, u0.w, ar1.z, ar1.w);
                        sdot = dot_h2(sdot, u1.x, ar2.x, ar2.y);
                        sdot = dot_h2(sdot, u1.y, ar2.z, ar2.w);
                        sdot = dot_h2(sdot, u1.z, ar3.x, ar3.y);
                        sdot = dot_h2(sdot, u1.w, ar3.z, ar3.w);
                        r2[q] = acc[m][ng][h * 2 + q] + __ldg(bias + o) + sc * sdot;
                    }
                    *reinterpret_cast<float2*>(orow + c0) = make_float2(r2[0], r2[1]);
                }
            }
        }
    }
}

// ---------------------------------------------------------------------------
// Launch
// ---------------------------------------------------------------------------
extern "C" void kernel_launch(void* const* d_in, const int* in_sizes, int n_in,
                              void* d_out, int out_size)
{
    const float* x           = (const float*)d_in[0];
    const int*   adapter_ids = (const int*)  d_in[1];
    const float* W_base      = (const float*)d_in[2];
    const float* b_base      = (const float*)d_in[3];
    const float* lora_A      = (const float*)d_in[4];
    const float* lora_B      = (const float*)d_in[5];
    const float* lora_scal   = (const float*)d_in[6];
    float*       out         = (float*)d_out;

    cudaFuncSetAttribute(gemm_mma_kernel,
                         cudaFuncAttributeMaxDynamicSharedMemorySize, DYN_BYTES);

    prepass_kernel<<<9217, 256>>>(x, W_base, lora_A, lora_B, adapter_ids);
    shrink_gemm_kernel<<<dim3(32, 4), 256>>>();
    gemm_mma_kernel<<<GRID_PERSIST, TPB, DYN_BYTES>>>(b_base, lora_scal, out);
}

// round 12
// speedup vs baseline: 6.5534x; 1.0040x over previous
#include <cuda_runtime.h>
#include <cuda_fp16.h>
#include <cstdint>

// ---------------- problem constants ----------------
#define N_TOK 4096
#define D_IN  2048
#define D_OUT 2048
#define RANK  16
#define MAX_LORAS 32

// ---------------- GEMM tiling ----------------
#define BM 128
#define BN 128
#define BK 64                 // fp16 elems per K-tile (128 bytes/row)
#define NKT (D_IN / BK)       // 32
#define TPB 256
#define STAGES 3
#define NTILES ((N_TOK / BM) * (D_OUT / BN))   // 512
#define GRID_PERSIST 304      // 2 CTAs/SM x 152 SMs (GB300)

#define ARR_BYTES (128 * 128)            // 16384 per tile array
#define STAGE_BYTES (2 * ARR_BYTES)      // A, B  (32768)
#define DYN_BYTES (STAGES * STAGE_BYTES) // 98304 -> 2 CTAs/SM

// XOR-SW128 swizzle: byte addr = row*128 + (col ^ ((row&7)<<4)), col in [0,128)
#define SWADDR(row, col) ((uint32_t)((row) * 128 + ((col) ^ (((row) & 7) << 4))))

// ---------------- device scratch (no runtime allocation allowed) ----------------
__device__ __align__(16) float  g_Ares[N_TOK * RANK];     // SORTED token order
__device__ __align__(16) __half g_Xi[N_TOK * D_IN];
__device__ __align__(16) __half g_Wi[D_OUT * D_IN];
__device__ __align__(16) __half g_Ai[MAX_LORAS * RANK * D_IN];
__device__ __align__(16) __half g_Bi[MAX_LORAS * D_OUT * RANK];
__device__ __align__(16) int    g_perm[N_TOK];            // sorted pos -> token
__device__ __align__(16) int    g_sortedAdp[N_TOK];       // sorted pos -> adapter
__device__ __align__(16) int    g_binStart[MAX_LORAS + 1];

// ---------------- PTX helpers (baseline-portable: sm_80-era ops) ----------------
__device__ __forceinline__ uint32_t smem_u32(const void* p) {
    uint32_t a;
    asm("{ .reg .u64 t; cvta.to.shared.u64 t, %1; cvt.u32.u64 %0, t; }" : "=r"(a) : "l"(p));
    return a;
}
#define CP16(dst, src) \
    asm volatile("cp.async.cg.shared.global [%0], [%1], 16;" :: "r"(dst), "l"(src) : "memory")
#define CP_COMMIT()  asm volatile("cp.async.commit_group;" ::: "memory")
#define CP_WAIT(n)   asm volatile("cp.async.wait_group %0;" :: "n"(n) : "memory")

__device__ __forceinline__ void ldsm4(uint32_t* r, uint32_t addr) {
    asm volatile("ldmatrix.sync.aligned.m8n8.x4.shared.b16 {%0,%1,%2,%3}, [%4];"
        : "=r"(r[0]), "=r"(r[1]), "=r"(r[2]), "=r"(r[3]) : "r"(addr));
}
__device__ __forceinline__ void mma_f16(float* d, const uint32_t* a,
                                        uint32_t b0, uint32_t b1) {
    asm volatile(
        "mma.sync.aligned.m16n8k16.row.col.f32.f16.f16.f32 "
        "{%0,%1,%2,%3}, {%4,%5,%6,%7}, {%8,%9}, {%0,%1,%2,%3};"
        : "+f"(d[0]), "+f"(d[1]), "+f"(d[2]), "+f"(d[3])
        : "r"(a[0]), "r"(a[1]), "r"(a[2]), "r"(a[3]), "r"(b0), "r"(b1));
}
__device__ __forceinline__ float dot_h2(float acc, uint32_t h2, float a0, float a1) {
    float2 f = __half22float2(*reinterpret_cast<__half2*>(&h2));
    return acc + a0 * f.x + a1 * f.y;
}
__device__ __forceinline__ uint2 f4_to_h4(float4 v) {
    __half2 p0 = __floats2half2_rn(v.x, v.y);
    __half2 p1 = __floats2half2_rn(v.z, v.w);
    uint2 u;
    u.x = *reinterpret_cast<uint32_t*>(&p0);
    u.y = *reinterpret_cast<uint32_t*>(&p1);
    return u;
}

// ---------------------------------------------------------------------------
// Kernel 1 (prepass), MLP=4 layout:
//   blocks [0, 2048):    X convert, 4 float4/thread (2M float4 total)
//   blocks [2048, 3072): W convert, 4 float4/thread (1M float4 total)
//   blocks [3072, 4096): loraA + loraB convert (2 streams/thread)
//   block  4096:         deterministic stable counting sort by adapter
// ---------------------------------------------------------------------------
__global__ __launch_bounds__(256) void prepass_kernel(
    const float* __restrict__ x, const float* __restrict__ w,
    const float* __restrict__ lora_A, const float* __restrict__ lora_B,
    const int* __restrict__ adapter_ids)
{
    const int bid = blockIdx.x;
    const int tid = threadIdx.x;

    if (bid < 2048) {                                // X: 2048*1024 = 2M float4
        const int base = bid * 1024 + tid;
        float4 v0 = reinterpret_cast<const float4*>(x)[base + 0 * 256];
        float4 v1 = reinterpret_cast<const float4*>(x)[base + 1 * 256];
        float4 v2 = reinterpret_cast<const float4*>(x)[base + 2 * 256];
        float4 v3 = reinterpret_cast<const float4*>(x)[base + 3 * 256];
        *reinterpret_cast<uint2*>(&g_Xi[(size_t)(base + 0 * 256) * 4]) = f4_to_h4(v0);
        *reinterpret_cast<uint2*>(&g_Xi[(size_t)(base + 1 * 256) * 4]) = f4_to_h4(v1);
        *reinterpret_cast<uint2*>(&g_Xi[(size_t)(base + 2 * 256) * 4]) = f4_to_h4(v2);
        *reinterpret_cast<uint2*>(&g_Xi[(size_t)(base + 3 * 256) * 4]) = f4_to_h4(v3);
        return;
    }
    if (bid < 3072) {                                // W: 1024*1024 = 1M float4
        const int base = (bid - 2048) * 1024 + tid;
        float4 v0 = reinterpret_cast<const float4*>(w)[base + 0 * 256];
        float4 v1 = reinterpret_cast<const float4*>(w)[base + 1 * 256];
        float4 v2 = reinterpret_cast<const float4*>(w)[base + 2 * 256];
        float4 v3 = reinterpret_cast<const float4*>(w)[base + 3 * 256];
        *reinterpret_cast<uint2*>(&g_Wi[(size_t)(base + 0 * 256) * 4]) = f4_to_h4(v0);
        *reinterpret_cast<uint2*>(&g_Wi[(size_t)(base + 1 * 256) * 4]) = f4_to_h4(v1);
        *reinterpret_cast<uint2*>(&g_Wi[(size_t)(base + 2 * 256) * 4]) = f4_to_h4(v2);
        *reinterpret_cast<uint2*>(&g_Wi[(size_t)(base + 3 * 256) * 4]) = f4_to_h4(v3);
        return;
    }
    if (bid < 4096) {                                // loraA/B: 1024*256 = 262144 f4
        const int idx = (bid - 3072) * 256 + tid;
        float4 va = reinterpret_cast<const float4*>(lora_A)[idx];
        float4 vb = reinterpret_cast<const float4*>(lora_B)[idx];
        *reinterpret_cast<uint2*>(&g_Ai[(size_t)idx * 4]) = f4_to_h4(va);
        *reinterpret_cast<uint2*>(&g_Bi[(size_t)idx * 4]) = f4_to_h4(vb);
        return;
    }

    // ---- sort block: stable counting sort of 4096 tokens into 32 bins ----
    __shared__ uint32_t hist[256 * 33];   // padded row stride 33 (bank spread)
    __shared__ uint32_t binTotal[32];
    __shared__ uint32_t binBase[33];

    int ids[16];
    #pragma unroll
    for (int j = 0; j < 33; j++) hist[tid * 33 + j] = 0;
    __syncthreads();
    #pragma unroll
    for (int j = 0; j < 16; j++) {
        ids[j] = adapter_ids[tid * 16 + j];
        hist[tid * 33 + ids[j]]++;
    }
    __syncthreads();
    if (tid < 32) {        // per-bin prefix over threads (stable base)
        uint32_t s = 0;
        for (int t = 0; t < 256; t++) {
            uint32_t c = hist[t * 33 + tid];
            hist[t * 33 + tid] = s;
            s += c;
        }
        binTotal[tid] = s;
    }
    __syncthreads();
    if (tid == 0) {
        uint32_t acc = 0;
        for (int b = 0; b < 32; b++) { binBase[b] = acc; acc += binTotal[b]; }
        binBase[32] = acc;   // = 4096
    }
    __syncthreads();
    #pragma unroll
    for (int j = 0; j < 16; j++) {       // stable scatter
        const int b = ids[j];
        const uint32_t off = hist[tid * 33 + b]++;
        const uint32_t pos = binBase[b] + off;
        g_perm[pos]      = tid * 16 + j;
        g_sortedAdp[pos] = b;
    }
    if (tid < 33) g_binStart[tid] = (int)binBase[tid];
}

// ---------------------------------------------------------------------------
// Kernel 2: shrink as per-adapter mma GEMM (unchanged from R11).
// Block (a, c): Ares[sorted base+r, :] = X[tok_r, :] . A[a]^T.
// ---------------------------------------------------------------------------
__global__ __launch_bounds__(256) void shrink_gemm_kernel()
{
    __shared__ __align__(16) char xs[2][16384];   // X tiles 128x64 fp16
    __shared__ __align__(16) char as_[2][2048];   // A tiles 16x64 fp16
    __shared__ int tokSh[128];

    const int a   = blockIdx.x;
    const int cy  = blockIdx.y;
    const int tid = threadIdx.x;
    const int wid = tid >> 5, lane = tid & 31;

    const int binS = g_binStart[a], binE = g_binStart[a + 1];
    const int base = binS + cy * 128;
    int cnt = binE - base;
    if (cnt <= 0) return;
    if (cnt > 128) cnt = 128;

    if (tid < 128) tokSh[tid] = g_perm[base + (tid < cnt ? tid : cnt - 1)];
    __syncthreads();

    const int ldCol = (tid & 7) * 16;
    auto load = [&](int kt, int stg) {
        #pragma unroll
        for (int i = 0; i < 4; i++) {
            const int c = tid + i * 256;          // 0..1023
            const int row = c >> 3;
            CP16(smem_u32(xs[stg]) + SWADDR(row, ldCol),
                 (const char*)g_Xi + (size_t)tokSh[row] * 4096 + kt * 128 + ldCol);
        }
        if (tid < 128) {
            const int row = tid >> 3;             // 0..15
            CP16(smem_u32(as_[stg]) + SWADDR(row, ldCol),
                 (const char*)g_Ai + ((size_t)a * RANK + row) * 4096 + kt * 128 + ldCol);
        }
        CP_COMMIT();
    };

    float acc2[2][4];
    #pragma unroll
    for (int i = 0; i < 2; i++)
        #pragma unroll
        for (int k = 0; k < 4; k++) acc2[i][k] = 0.f;

    const int lmRow = lane & 15, lmChunk = (lane >> 4) * 16;

    load(0, 0);
    for (int kt = 0; kt < NKT; kt++) {
        if (kt + 1 < NKT) load(kt + 1, (kt + 1) & 1); else CP_COMMIT();
        CP_WAIT(1);
        __syncthreads();
        const uint32_t xb = smem_u32(xs[kt & 1]);
        const uint32_t ab = smem_u32(as_[kt & 1]);
        #pragma unroll
        for (int s = 0; s < 4; s++) {
            uint32_t xh[4], bh[4];
            ldsm4(xh, xb + SWADDR(wid * 16 + lmRow, s * 32 + lmChunk));
            ldsm4(bh, ab + SWADDR(lmRow,           s * 32 + lmChunk));
            mma_f16(acc2[0], xh, bh[0], bh[2]);
            mma_f16(acc2[1], xh, bh[1], bh[3]);
        }
        __syncthreads();   // protect stage (kt+1)&1 reuse next iteration
    }

    const int gID = lane >> 2, tig = lane & 3;
    #pragma unroll
    for (int h = 0; h < 2; h++) {
        const int r = wid * 16 + gID + h * 8;
        if (r < cnt) {
            float* dst = g_Ares + (size_t)(base + r) * RANK;
            #pragma unroll
            for (int ng = 0; ng < 2; ng++) {
                const int c = ng * 8 + 2 * tig;
                *reinterpret_cast<float2*>(dst + c) =
                    make_float2(acc2[ng][h * 2], acc2[ng][h * 2 + 1]);
            }
        }
    }
}

// ---------------------------------------------------------------------------
// Kernel 3: persistent fp16 mma.sync GEMM over SORTED token rows + fused
// LoRA expand epilogue (unchanged from R11).
// ---------------------------------------------------------------------------
__global__ __launch_bounds__(TPB, 2) void gemm_mma_kernel(
    const float* __restrict__ bias,
    const float* __restrict__ scaling,
    float*       __restrict__ out)
{
    extern __shared__ char dsm[];
    __shared__ __align__(16) float AresSh[BM][RANK];
    __shared__ int   adSh[BM];
    __shared__ float scSh[BM];
    __shared__ int   tokSh[BM];

    const int tid  = threadIdx.x;
    const int wid  = tid >> 5, lane = tid & 31;
    const int warpM = wid >> 2;          // 0..1 (64 rows)
    const int warpN = wid & 3;           // 0..3 (32 cols)

    const uint32_t dynb = smem_u32(dsm);
    const int lmRow   = lane & 15;
    const int lmChunk = (lane >> 4) * 16;
    const int aRow0 = warpM * 64 + lmRow;
    const int bRow0 = warpN * 32 + lmRow;
    const int ldCol = (tid & 7) * 16;

    for (unsigned int t = blockIdx.x; t < NTILES; t += gridDim.x) {
        // WAR guard: prior tile's epilogue reads of smem preload arrays
        __syncthreads();

        const int rowBlock = (int)(t >> 4) * BM;     // sorted-row block
        const int colBlock = (int)(t & 15) * BN;

        // preload: Ares rows (sorted-contiguous), adapters, scales, tokens
        {
            const float4* ag  = reinterpret_cast<const float4*>(g_Ares + (size_t)rowBlock * RANK);
            float4*       as4 = reinterpret_cast<float4*>(&AresSh[0][0]);
            as4[tid]       = ag[tid];
            as4[tid + 256] = ag[tid + 256];
            if (tid < BM) {
                const int sp = rowBlock + tid;
                const int a  = g_sortedAdp[sp];
                adSh[tid]  = a;
                scSh[tid]  = scaling[a];
                tokSh[tid] = g_perm[sp];
            }
        }
        __syncthreads();   // tokSh ready before gathered loads

        const char* srcW = (const char*)(g_Wi + (size_t)colBlock * D_IN);

        auto load_tile = [&](int kt, int stg) {
            const uint32_t sb = dynb + stg * STAGE_BYTES;
            const size_t koff = (size_t)kt * (BK * 2);   // 128 B per row
            #pragma unroll
            for (int i = 0; i < 4; i++) {
                const int c   = tid + i * 256;           // 0..1023
                const int row = c >> 3;
                const uint32_t d = SWADDR(row, ldCol);
                CP16(sb + 0 * ARR_BYTES + d,
                     (const char*)g_Xi + (size_t)tokSh[row] * (D_IN * 2) + koff + ldCol);
                CP16(sb + 1 * ARR_BYTES + d,
                     srcW + (size_t)row * (D_IN * 2) + koff + ldCol);
            }
            CP_COMMIT();
        };

        float acc[4][4][4];
        #pragma unroll
        for (int m = 0; m < 4; m++)
            #pragma unroll
            for (int n = 0; n < 4; n++)
                #pragma unroll
                for (int k = 0; k < 4; k++) acc[m][n][k] = 0.f;

        load_tile(0, 0);
        load_tile(1, 1);

        for (int kt = 0; kt < NKT; kt++) {
            const int stg = kt % STAGES;
            CP_WAIT(STAGES - 2);
            __syncthreads();
            if (kt + STAGES - 1 < NKT)
                load_tile(kt + STAGES - 1, (kt + STAGES - 1) % STAGES);
            else
                CP_COMMIT();   // empty group keeps wait accounting exact

            const uint32_t sb = dynb + stg * STAGE_BYTES;
            const uint32_t aArr = sb + 0 * ARR_BYTES;
            const uint32_t bArr = sb + 1 * ARR_BYTES;

            #pragma unroll
            for (int s = 0; s < 4; s++) {
                const int ko = s * 32;
                uint32_t ah[4][4], bh[2][4];
                #pragma unroll
                for (int m = 0; m < 4; m++)
                    ldsm4(ah[m], aArr + SWADDR(aRow0 + m * 16, ko + lmChunk));
                #pragma unroll
                for (int g = 0; g < 2; g++)
                    ldsm4(bh[g], bArr + SWADDR(bRow0 + g * 16, ko + lmChunk));
                #pragma unroll
                for (int m = 0; m < 4; m++)
                    #pragma unroll
                    for (int ng = 0; ng < 4; ng++) {
                        const int g = ng >> 1, sub = ng & 1;
                        mma_f16(acc[m][ng], ah[m], bh[g][sub], bh[g][sub + 2]);
                    }
            }
        }
        CP_WAIT(0);   // drain before next tile reuses stages

        // ---- epilogue: acc + bias + scale * (Ares . loraB_fp16[a, o, :]) ----
        const int gID = lane >> 2, tig = lane & 3;
        #pragma unroll
        for (int m = 0; m < 4; m++) {
            #pragma unroll
            for (int h = 0; h < 2; h++) {
                const int rl = warpM * 64 + m * 16 + gID + h * 8;
                const int tok = tokSh[rl];
                const int a   = adSh[rl];
                const float sc = scSh[rl];
                const float* ar = &AresSh[rl][0];
                const float4 ar0 = *reinterpret_cast<const float4*>(ar + 0);
                const float4 ar1 = *reinterpret_cast<const float4*>(ar + 4);
                const float4 ar2 = *reinterpret_cast<const float4*>(ar + 8);
                const float4 ar3 = *reinterpret_cast<const float4*>(ar + 12);
                const __half* Bb = g_Bi + (size_t)a * D_OUT * RANK;
                float* orow = out + (size_t)tok * D_OUT + colBlock;

                #pragma unroll
                for (int ng = 0; ng < 4; ng++) {
                    const int c0 = warpN * 32 + ng * 8 + 2 * tig;
                    float r2[2];
                    #pragma unroll
                    for (int q = 0; q < 2; q++) {
                        const int o = colBlock + c0 + q;
                        const uint4* Bp = reinterpret_cast<const uint4*>(Bb + (size_t)o * RANK);
                        uint4 u0 = __ldg(Bp);
                        uint4 u1 = __ldg(Bp + 1);
                        float sdot = 0.f;
                        sdot = dot_h2(sdot, u0.x, ar0.x, ar0.y);
                        sdot = dot_h2(sdot, u0.y, ar0.z, ar0.w);
                        sdot = dot_h2(sdot, u0.z, ar1.x, ar1.y);
                        sdot = dot_h2(sdot, u0.w, ar1.z, ar1.w);
                        sdot = dot_h2(sdot, u1.x, ar2.x, ar2.y);
                        sdot = dot_h2(sdot, u1.y, ar2.z, ar2.w);
                        sdot = dot_h2(sdot, u1.z, ar3.x, ar3.y);
                        sdot = dot_h2(sdot, u1.w, ar3.z, ar3.w);
                        r2[q] = acc[m][ng][h * 2 + q] + __ldg(bias + o) + sc * sdot;
                    }
                    *reinterpret_cast<float2*>(orow + c0) = make_float2(r2[0], r2[1]);
                }
            }
        }
    }
}

// ---------------------------------------------------------------------------
// Launch
// ---------------------------------------------------------------------------
extern "C" void kernel_launch(void* const* d_in, const int* in_sizes, int n_in,
                              void* d_out, int out_size)
{
    const float* x           = (const float*)d_in[0];
    const int*   adapter_ids = (const int*)  d_in[1];
    const float* W_base      = (const float*)d_in[2];
    const float* b_base      = (const float*)d_in[3];
    const float* lora_A      = (const float*)d_in[4];
    const float* lora_B      = (const float*)d_in[5];
    const float* lora_scal   = (const float*)d_in[6];
    float*       out         = (float*)d_out;

    cudaFuncSetAttribute(gemm_mma_kernel,
                         cudaFuncAttributeMaxDynamicSharedMemorySize, DYN_BYTES);

    prepass_kernel<<<4097, 256>>>(x, W_base, lora_A, lora_B, adapter_ids);
    shrink_gemm_kernel<<<dim3(32, 4), 256>>>();
    gemm_mma_kernel<<<GRID_PERSIST, TPB, DYN_BYTES>>>(b_base, lora_scal, out);
}